// round 3
// baseline (speedup 1.0000x reference)
#include <cuda_runtime.h>
#include <math.h>

// ---------------- constants ----------------
#define NBATCH 4
#define TTOP   65536          // input length
// output layout (float32): x_hat | loss | ids | similarity
#define OFF_XHAT 0
#define OFF_LOSS 262144       // 4*65536
#define OFF_IDS  262145
#define OFF_SIM  294913       // 262145 + 4*8192
#define NEMB 512

#define ALIGN4(n) (((n) + 3) & ~3)

typedef unsigned long long u64;

#define FMA2(d, a, b, c) \
    asm("fma.rn.f32x2 %0, %1, %2, %3;" : "=l"(d) : "l"(a), "l"(b), "l"(c))
#define PACK2(out, lo, hi) \
    asm("mov.b64 %0, {%1, %2};" : "=l"(out) : "f"(lo), "f"(hi))
#define UNPACK2(lo, hi, in) \
    asm("mov.b64 {%0, %1}, %2;" : "=f"(lo), "=f"(hi) : "l"(in))

// ---------------- scratch (no allocation allowed) ----------------
__device__ float g_A[16777216];   // 4*65536*64
__device__ float g_B[16777216];
__device__ float g_ne[NEMB];
__device__ float g_rsne[NEMB];
__device__ float g_loss;

// ---------------- tiny kernels ----------------
__global__ void zero_loss_kernel() { g_loss = 0.f; }

__global__ void ne_kernel(const float* __restrict__ cb) {
    int e = blockIdx.x * blockDim.x + threadIdx.x;
    if (e < NEMB) {
        float s = 0.f;
        #pragma unroll 8
        for (int ci = 0; ci < 64; ci++) { float v = cb[e * 64 + ci]; s += v * v; }
        g_ne[e] = s;
        g_rsne[e] = rsqrtf(s);
    }
}

__global__ void loss_fin_kernel(float* __restrict__ out) {
    out[OFF_LOSS] = 1.25f * g_loss / 32768.0f;
}

// ---------------- first conv: Cin=1 -> 64, K=4, stride 2, ReLU ----------------
__global__ void __launch_bounds__(256) down0_kernel(
    const float* __restrict__ x, const float* __restrict__ w,
    const float* __restrict__ bias, float* __restrict__ y)
{
    __shared__ float ws[256];   // (4,64)
    __shared__ float bs[64];
    int tid = threadIdx.x;
    ws[tid] = w[tid];
    if (tid < 64) bs[tid] = bias[tid];
    __syncthreads();

    int g = blockIdx.x * 256 + tid;          // total = 4*32768*4
    int q = g & 3;
    int rest = g >> 2;
    int ot = rest & 32767;
    int b = rest >> 15;

    float acc[16];
    #pragma unroll
    for (int c = 0; c < 16; c++) acc[c] = bs[q * 16 + c];
    #pragma unroll
    for (int k = 0; k < 4; k++) {
        int t = 2 * ot - 1 + k;
        float xv = (t >= 0 && t < TTOP) ? x[(size_t)b * TTOP + t] : 0.f;
        #pragma unroll
        for (int c = 0; c < 16; c++) acc[c] += xv * ws[k * 64 + q * 16 + c];
    }
    float* op = y + ((size_t)(b * 32768 + ot)) * 64 + q * 16;
    #pragma unroll
    for (int c4 = 0; c4 < 4; c4++) {
        float4 o;
        o.x = fmaxf(acc[c4 * 4 + 0], 0.f);
        o.y = fmaxf(acc[c4 * 4 + 1], 0.f);
        o.z = fmaxf(acc[c4 * 4 + 2], 0.f);
        o.w = fmaxf(acc[c4 * 4 + 3], 0.f);
        *(float4*)(op + c4 * 4) = o;
    }
}

// ---------------- residual conv: K=3, dil DIL, 64->64, ReLU, optional +res ----
// Tile: 128 time x 64 ch. x transposed+swizzled in smem, all 3 weight taps
// resident, inner math in packed f32x2 (co pairs).
#define XS_STRIDE 160
#define SMEM_RES ((64 * XS_STRIDE + 3 * 4096) * 4)

template<int DIL, bool RES>
__global__ void __launch_bounds__(256, 2) conv_res_kernel(
    const float* __restrict__ x, const float* __restrict__ w,
    const float* __restrict__ bias, const float* __restrict__ res,
    float* __restrict__ y, int T)
{
    extern __shared__ float smem[];
    float* xsT = smem;                    // [64][XS_STRIDE], swizzled
    float* wsm = smem + 64 * XS_STRIDE;   // [3][64][64]

    const int tid = threadIdx.x;
    const int tilesPerB = T >> 7;
    const int b = blockIdx.x / tilesPerB;
    const int t0 = (blockIdx.x - b * tilesPerB) << 7;
    const float* xb = x + (size_t)b * T * 64;

    constexpr int ROWS = 128 + 2 * DIL;
    constexpr int NR4 = (ROWS + 3) >> 2;

    // stage x transposed with xor swizzle (conflict-free STS.128)
    for (int idx = tid; idx < 64 * NR4; idx += 256) {
        int ci = idx & 63;
        int rb = (idx >> 6) << 2;
        float v0 = 0.f, v1 = 0.f, v2 = 0.f, v3 = 0.f;
        int gt = t0 - DIL + rb;
        if (gt + 0 >= 0 && gt + 0 < T && rb + 0 < ROWS) v0 = xb[(size_t)(gt + 0) * 64 + ci];
        if (gt + 1 >= 0 && gt + 1 < T && rb + 1 < ROWS) v1 = xb[(size_t)(gt + 1) * 64 + ci];
        if (gt + 2 >= 0 && gt + 2 < T && rb + 2 < ROWS) v2 = xb[(size_t)(gt + 2) * 64 + ci];
        if (gt + 3 >= 0 && gt + 3 < T && rb + 3 < ROWS) v3 = xb[(size_t)(gt + 3) * 64 + ci];
        int sw = (ci & 7) << 2;
        *(float4*)&xsT[ci * XS_STRIDE + (rb ^ sw)] = make_float4(v0, v1, v2, v3);
    }
    // stage all 3 weight taps
    {
        const float4* wg = (const float4*)w;
        float4* wd = (float4*)wsm;
        for (int idx = tid; idx < 3072; idx += 256) wd[idx] = wg[idx];
    }
    __syncthreads();

    const int tg = tid >> 3;        // 0..31 -> time base tg*4
    const int cg = tid & 7;         // co group: co0 = cg*8
    const int tb = tg << 2;
    constexpr int W = 2 * DIL + 4;  // x window length per ci

    u64 acc[4][4];
    #pragma unroll
    for (int i = 0; i < 4; i++)
        #pragma unroll
        for (int j = 0; j < 4; j++) acc[i][j] = 0ull;

    const float* wrow = wsm + cg * 8;

    for (int ci = 0; ci < 64; ci++) {
        const float* xr = &xsT[ci * XS_STRIDE];
        const int sw = (ci & 7) << 2;
        float xw[12];
        float4 c0 = *(const float4*)&xr[(tb + 0) ^ sw];
        float4 c1 = *(const float4*)&xr[(tb + 4) ^ sw];
        xw[0] = c0.x; xw[1] = c0.y; xw[2] = c0.z; xw[3] = c0.w;
        xw[4] = c1.x; xw[5] = c1.y; xw[6] = c1.z; xw[7] = c1.w;
        if (DIL == 3) {
            float4 c2 = *(const float4*)&xr[(tb + 8) ^ sw];
            xw[8] = c2.x; xw[9] = c2.y; xw[10] = c2.z; xw[11] = c2.w;
        }
        u64 xd[W];
        #pragma unroll
        for (int m = 0; m < W; m++) PACK2(xd[m], xw[m], xw[m]);

        const float* wci = wrow + ci * 64;
        #pragma unroll
        for (int k = 0; k < 3; k++) {
            union { float4 f; u64 u[2]; } W0, W1;
            W0.f = *(const float4*)(wci + k * 4096);
            W1.f = *(const float4*)(wci + k * 4096 + 4);
            #pragma unroll
            for (int i = 0; i < 4; i++) {
                u64 xv = xd[i + k * DIL];
                FMA2(acc[i][0], xv, W0.u[0], acc[i][0]);
                FMA2(acc[i][1], xv, W0.u[1], acc[i][1]);
                FMA2(acc[i][2], xv, W1.u[0], acc[i][2]);
                FMA2(acc[i][3], xv, W1.u[1], acc[i][3]);
            }
        }
    }

    const int co0 = cg * 8;
    float4 bv0 = *(const float4*)(bias + co0);
    float4 bv1 = *(const float4*)(bias + co0 + 4);
    #pragma unroll
    for (int i = 0; i < 4; i++) {
        int gt = t0 + tb + i;
        float o[8];
        UNPACK2(o[0], o[1], acc[i][0]);
        UNPACK2(o[2], o[3], acc[i][1]);
        UNPACK2(o[4], o[5], acc[i][2]);
        UNPACK2(o[6], o[7], acc[i][3]);
        float4 q0, q1;
        q0.x = fmaxf(o[0] + bv0.x, 0.f);
        q0.y = fmaxf(o[1] + bv0.y, 0.f);
        q0.z = fmaxf(o[2] + bv0.z, 0.f);
        q0.w = fmaxf(o[3] + bv0.w, 0.f);
        q1.x = fmaxf(o[4] + bv1.x, 0.f);
        q1.y = fmaxf(o[5] + bv1.y, 0.f);
        q1.z = fmaxf(o[6] + bv1.z, 0.f);
        q1.w = fmaxf(o[7] + bv1.w, 0.f);
        float* op = y + ((size_t)b * T + gt) * 64 + co0;
        if (RES) {
            const float* rp = res + ((size_t)b * T + gt) * 64 + co0;
            float4 r0 = *(const float4*)rp;
            float4 r1 = *(const float4*)(rp + 4);
            q0.x += r0.x; q0.y += r0.y; q0.z += r0.z; q0.w += r0.w;
            q1.x += r1.x; q1.y += r1.y; q1.z += r1.z; q1.w += r1.w;
        }
        *(float4*)op = q0;
        *(float4*)(op + 4) = q1;
    }
}

// ---------------- strided down conv: K=4, stride 2, 64->64, ReLU ----------------
__global__ void __launch_bounds__(256, 2) conv_s2_kernel(
    const float* __restrict__ x, const float* __restrict__ w,
    const float* __restrict__ bias, float* __restrict__ y, int Tout)
{
    extern __shared__ float smem[];
    float* xs = smem;                           // [258][65]
    float* wsm = smem + ALIGN4(258 * 65);       // [64][64]
    const int Tin = Tout << 1;
    const int tid = threadIdx.x;
    const int tilesPerB = Tout >> 7;
    const int b = blockIdx.x / tilesPerB;
    const int t0 = (blockIdx.x - b * tilesPerB) << 7;
    const float* xb = x + (size_t)b * Tin * 64;

    for (int idx = tid; idx < 258 * 16; idx += 256) {
        int r = idx >> 4, c4 = idx & 15;
        int gt = 2 * t0 - 1 + r;
        float4 v = make_float4(0.f, 0.f, 0.f, 0.f);
        if (gt >= 0 && gt < Tin) v = *(const float4*)(xb + (size_t)gt * 64 + c4 * 4);
        float* d = &xs[r * 65 + c4 * 4];
        d[0] = v.x; d[1] = v.y; d[2] = v.z; d[3] = v.w;
    }

    const int tg = tid >> 3;
    const int cg = tid & 7;
    float acc[4][8];
    #pragma unroll
    for (int i = 0; i < 4; i++)
        #pragma unroll
        for (int j = 0; j < 8; j++) acc[i][j] = 0.f;

    for (int k = 0; k < 4; k++) {
        __syncthreads();
        {
            const float4* wg = (const float4*)(w + k * 4096);
            float4* wd = (float4*)wsm;
            for (int idx = tid; idx < 1024; idx += 256) wd[idx] = wg[idx];
        }
        __syncthreads();
        const float4* ws4 = (const float4*)wsm;
        #pragma unroll 2
        for (int ci = 0; ci < 64; ci++) {
            float4 wa = ws4[ci * 16 + cg * 2];
            float4 wb = ws4[ci * 16 + cg * 2 + 1];
            #pragma unroll
            for (int i = 0; i < 4; i++) {
                float xv = xs[(2 * (tg * 4 + i) + k) * 65 + ci];
                acc[i][0] += xv * wa.x; acc[i][1] += xv * wa.y;
                acc[i][2] += xv * wa.z; acc[i][3] += xv * wa.w;
                acc[i][4] += xv * wb.x; acc[i][5] += xv * wb.y;
                acc[i][6] += xv * wb.z; acc[i][7] += xv * wb.w;
            }
        }
    }

    const int co0 = cg * 8;
    float4 bv0 = *(const float4*)(bias + co0);
    float4 bv1 = *(const float4*)(bias + co0 + 4);
    #pragma unroll
    for (int i = 0; i < 4; i++) {
        int gt = t0 + tg * 4 + i;
        float* op = y + ((size_t)b * Tout + gt) * 64 + co0;
        float4 o0, o1;
        o0.x = fmaxf(acc[i][0] + bv0.x, 0.f);
        o0.y = fmaxf(acc[i][1] + bv0.y, 0.f);
        o0.z = fmaxf(acc[i][2] + bv0.z, 0.f);
        o0.w = fmaxf(acc[i][3] + bv0.w, 0.f);
        o1.x = fmaxf(acc[i][4] + bv1.x, 0.f);
        o1.y = fmaxf(acc[i][5] + bv1.y, 0.f);
        o1.z = fmaxf(acc[i][6] + bv1.z, 0.f);
        o1.w = fmaxf(acc[i][7] + bv1.w, 0.f);
        *(float4*)op = o0;
        *(float4*)(op + 4) = o1;
    }
}

// ---------------- transposed conv: K=4, stride 2, 64->64, ReLU ----------------
__global__ void __launch_bounds__(256, 2) conv_tr_kernel(
    const float* __restrict__ x, const float* __restrict__ w,
    const float* __restrict__ bias, float* __restrict__ y, int Tout)
{
    extern __shared__ float smem[];
    float* xs = smem;                           // [130][65]
    float* wsm = smem + ALIGN4(130 * 65);       // [4][64][64]
    const int Tin = Tout >> 1;
    const int tid = threadIdx.x;
    const int tilesPerB = Tout >> 8;
    const int b = blockIdx.x / tilesPerB;
    const int t0 = (blockIdx.x - b * tilesPerB) << 8;
    const float* xb = x + (size_t)b * Tin * 64;
    const int in0 = (t0 >> 1) - 1;

    for (int idx = tid; idx < 130 * 16; idx += 256) {
        int r = idx >> 4, c4 = idx & 15;
        int gt = in0 + r;
        float4 v = make_float4(0.f, 0.f, 0.f, 0.f);
        if (gt >= 0 && gt < Tin) v = *(const float4*)(xb + (size_t)gt * 64 + c4 * 4);
        float* d = &xs[r * 65 + c4 * 4];
        d[0] = v.x; d[1] = v.y; d[2] = v.z; d[3] = v.w;
    }
    {
        const float4* wg = (const float4*)w;
        float4* wd = (float4*)wsm;
        for (int idx = tid; idx < 4096; idx += 256) wd[idx] = wg[idx];
    }
    __syncthreads();

    const int tg = tid >> 3;
    const int cg = tid & 7;
    float acc[8][8];
    #pragma unroll
    for (int i = 0; i < 8; i++)
        #pragma unroll
        for (int j = 0; j < 8; j++) acc[i][j] = 0.f;

    const float4* ws4 = (const float4*)wsm;
    #pragma unroll 2
    for (int ci = 0; ci < 64; ci++) {
        float xv[6];
        #pragma unroll
        for (int m = 0; m < 6; m++) xv[m] = xs[(tg * 4 + m) * 65 + ci];
        {
            float4 wa0 = ws4[ci * 16 + cg * 2];
            float4 wb0 = ws4[ci * 16 + cg * 2 + 1];
            float4 wa2 = ws4[2 * 1024 + ci * 16 + cg * 2];
            float4 wb2 = ws4[2 * 1024 + ci * 16 + cg * 2 + 1];
            #pragma unroll
            for (int ii = 0; ii < 4; ii++) {
                const int i = 2 * ii;
                float xa = xv[ii], xbv = xv[ii + 1];
                acc[i][0] += xa * wa0.x + xbv * wa2.x;
                acc[i][1] += xa * wa0.y + xbv * wa2.y;
                acc[i][2] += xa * wa0.z + xbv * wa2.z;
                acc[i][3] += xa * wa0.w + xbv * wa2.w;
                acc[i][4] += xa * wb0.x + xbv * wb2.x;
                acc[i][5] += xa * wb0.y + xbv * wb2.y;
                acc[i][6] += xa * wb0.z + xbv * wb2.z;
                acc[i][7] += xa * wb0.w + xbv * wb2.w;
            }
        }
        {
            float4 wa1 = ws4[1024 + ci * 16 + cg * 2];
            float4 wb1 = ws4[1024 + ci * 16 + cg * 2 + 1];
            float4 wa3 = ws4[3 * 1024 + ci * 16 + cg * 2];
            float4 wb3 = ws4[3 * 1024 + ci * 16 + cg * 2 + 1];
            #pragma unroll
            for (int ii = 0; ii < 4; ii++) {
                const int i = 2 * ii + 1;
                float xa = xv[ii + 1], xbv = xv[ii + 2];
                acc[i][0] += xa * wa1.x + xbv * wa3.x;
                acc[i][1] += xa * wa1.y + xbv * wa3.y;
                acc[i][2] += xa * wa1.z + xbv * wa3.z;
                acc[i][3] += xa * wa1.w + xbv * wa3.w;
                acc[i][4] += xa * wb1.x + xbv * wb3.x;
                acc[i][5] += xa * wb1.y + xbv * wb3.y;
                acc[i][6] += xa * wb1.z + xbv * wb3.z;
                acc[i][7] += xa * wb1.w + xbv * wb3.w;
            }
        }
    }

    const int co0 = cg * 8;
    float4 bv0 = *(const float4*)(bias + co0);
    float4 bv1 = *(const float4*)(bias + co0 + 4);
    #pragma unroll
    for (int i = 0; i < 8; i++) {
        int gt = t0 + tg * 8 + i;
        float* op = y + ((size_t)b * Tout + gt) * 64 + co0;
        float4 o0, o1;
        o0.x = fmaxf(acc[i][0] + bv0.x, 0.f);
        o0.y = fmaxf(acc[i][1] + bv0.y, 0.f);
        o0.z = fmaxf(acc[i][2] + bv0.z, 0.f);
        o0.w = fmaxf(acc[i][3] + bv0.w, 0.f);
        o1.x = fmaxf(acc[i][4] + bv1.x, 0.f);
        o1.y = fmaxf(acc[i][5] + bv1.y, 0.f);
        o1.z = fmaxf(acc[i][6] + bv1.z, 0.f);
        o1.w = fmaxf(acc[i][7] + bv1.w, 0.f);
        *(float4*)op = o0;
        *(float4*)(op + 4) = o1;
    }
}

// ---------------- final projection: K=3, dil 1, 64->1, linear ----------------
__global__ void __launch_bounds__(256) proj_kernel(
    const float* __restrict__ x, const float* __restrict__ w,
    const float* __restrict__ bias, float* __restrict__ out, int T)
{
    extern __shared__ float smem[];
    float* xs = smem;                           // [258][65]
    float* ws = smem + ALIGN4(258 * 65);        // [192]
    const int tid = threadIdx.x;
    const int tilesPerB = T >> 8;
    const int b = blockIdx.x / tilesPerB;
    const int t0 = (blockIdx.x - b * tilesPerB) << 8;
    const float* xb = x + (size_t)b * T * 64;

    for (int idx = tid; idx < 258 * 16; idx += 256) {
        int r = idx >> 4, c4 = idx & 15;
        int gt = t0 - 1 + r;
        float4 v = make_float4(0.f, 0.f, 0.f, 0.f);
        if (gt >= 0 && gt < T) v = *(const float4*)(xb + (size_t)gt * 64 + c4 * 4);
        float* d = &xs[r * 65 + c4 * 4];
        d[0] = v.x; d[1] = v.y; d[2] = v.z; d[3] = v.w;
    }
    if (tid < 192) ws[tid] = w[tid];
    __syncthreads();

    float acc = 0.f;
    #pragma unroll
    for (int k = 0; k < 3; k++) {
        #pragma unroll 8
        for (int ci = 0; ci < 64; ci++)
            acc += xs[(tid + k) * 65 + ci] * ws[k * 64 + ci];
    }
    out[OFF_XHAT + (size_t)b * T + t0 + tid] = acc + bias[0];
}

// ---------------- VQ: dot / dist / argmin / z_q / similarity / loss ----------------
__global__ void __launch_bounds__(256) vq_kernel(
    const float* __restrict__ ze, const float* __restrict__ cb,
    float* __restrict__ zq, float* __restrict__ dout)
{
    __shared__ float zs[32 * 65];
    __shared__ float cbs[128 * 65];
    __shared__ float nzs[32], rsnzs[32];

    const int tid = threadIdx.x;
    const int rg = tid >> 5;
    const int eg = tid & 31;
    const int row0 = blockIdx.x * 32;

    for (int idx = tid; idx < 32 * 16; idx += 256) {
        int r = idx >> 4, c4 = idx & 15;
        float4 v = *(const float4*)(ze + (size_t)(row0 + r) * 64 + c4 * 4);
        float* d = &zs[r * 65 + c4 * 4];
        d[0] = v.x; d[1] = v.y; d[2] = v.z; d[3] = v.w;
    }
    __syncthreads();
    if (tid < 32) {
        float s = 0.f;
        #pragma unroll 8
        for (int ci = 0; ci < 64; ci++) { float v = zs[tid * 65 + ci]; s += v * v; }
        nzs[tid] = s;
        rsnzs[tid] = rsqrtf(s);
    }

    float bv[4] = {3.4e38f, 3.4e38f, 3.4e38f, 3.4e38f};
    int bi[4] = {0, 0, 0, 0};

    for (int c = 0; c < 4; c++) {
        __syncthreads();
        for (int idx = tid; idx < 128 * 16; idx += 256) {
            int e = idx >> 4, c4 = idx & 15;
            float4 v = *(const float4*)(cb + (size_t)(c * 128 + e) * 64 + c4 * 4);
            float* d = &cbs[e * 65 + c4 * 4];
            d[0] = v.x; d[1] = v.y; d[2] = v.z; d[3] = v.w;
        }
        __syncthreads();

        float acc[4][4];
        #pragma unroll
        for (int i = 0; i < 4; i++)
            #pragma unroll
            for (int j = 0; j < 4; j++) acc[i][j] = 0.f;

        #pragma unroll 4
        for (int ci = 0; ci < 64; ci++) {
            float zv[4], cv[4];
            #pragma unroll
            for (int i = 0; i < 4; i++) zv[i] = zs[(rg * 4 + i) * 65 + ci];
            #pragma unroll
            for (int j = 0; j < 4; j++) cv[j] = cbs[(j * 32 + eg) * 65 + ci];
            #pragma unroll
            for (int i = 0; i < 4; i++)
                #pragma unroll
                for (int j = 0; j < 4; j++) acc[i][j] += zv[i] * cv[j];
        }

        #pragma unroll
        for (int j = 0; j < 4; j++) {
            int e = c * 128 + j * 32 + eg;
            float nev = __ldg(&g_ne[e]);
            float rse = __ldg(&g_rsne[e]);
            #pragma unroll
            for (int i = 0; i < 4; i++) {
                int r = rg * 4 + i;
                float dot = acc[i][j];
                float dist = -2.0f * dot + nzs[r] + nev;
                float sim = dot * rsnzs[r] * rse;
                dout[OFF_SIM + (size_t)(row0 + r) * NEMB + e] = sim;
                if (dist < bv[i]) { bv[i] = dist; bi[i] = e; }
            }
        }
    }

    #pragma unroll
    for (int i = 0; i < 4; i++) {
        float v = bv[i];
        int idx = bi[i];
        #pragma unroll
        for (int off = 16; off > 0; off >>= 1) {
            float ov = __shfl_down_sync(0xffffffffu, v, off);
            int oi = __shfl_down_sync(0xffffffffu, idx, off);
            if (ov < v || (ov == v && oi < idx)) { v = ov; idx = oi; }
        }
        if (eg == 0) {
            int r = rg * 4 + i;
            int gr = row0 + r;
            dout[OFF_IDS + gr] = (float)idx;
            float s = 0.f;
            const float* cp = cb + (size_t)idx * 64;
            float* qp = zq + (size_t)gr * 64;
            #pragma unroll 8
            for (int ci = 0; ci < 64; ci++) {
                float cvv = __ldg(cp + ci);
                qp[ci] = cvv;
                float d = zs[r * 65 + ci] - cvv;
                s += d * d;
            }
            atomicAdd(&g_loss, sqrtf(s));
        }
    }
}

// ---------------- host orchestration ----------------
#define SMEM_S2   ((ALIGN4(258 * 65) + 4096) * 4)
#define SMEM_TR   ((ALIGN4(130 * 65) + 16384) * 4)
#define SMEM_PROJ ((ALIGN4(258 * 65) + 192) * 4)

extern "C" void kernel_launch(void* const* d_in, const int* in_sizes, int n_in,
                              void* d_out, int out_size)
{
    const float* x        = (const float*)d_in[0];
    const float* w_down0  = (const float*)d_in[1];
    const float* b_down0  = (const float*)d_in[2];
    const float* w_down   = (const float*)d_in[3];
    const float* b_down   = (const float*)d_in[4];
    const float* w_res_e  = (const float*)d_in[5];
    const float* b_res_e  = (const float*)d_in[6];
    const float* codebook = (const float*)d_in[7];
    const float* w_res_d  = (const float*)d_in[8];
    const float* b_res_d  = (const float*)d_in[9];
    const float* w_up     = (const float*)d_in[10];
    const float* b_up     = (const float*)d_in[11];
    const float* w_proj   = (const float*)d_in[12];
    const float* b_proj   = (const float*)d_in[13];
    float* out = (float*)d_out;

    float *A, *Bb;
    cudaGetSymbolAddress((void**)&A, g_A);
    cudaGetSymbolAddress((void**)&Bb, g_B);

    cudaFuncSetAttribute(conv_res_kernel<3, false>, cudaFuncAttributeMaxDynamicSharedMemorySize, SMEM_RES);
    cudaFuncSetAttribute(conv_res_kernel<3, true>,  cudaFuncAttributeMaxDynamicSharedMemorySize, SMEM_RES);
    cudaFuncSetAttribute(conv_res_kernel<1, false>, cudaFuncAttributeMaxDynamicSharedMemorySize, SMEM_RES);
    cudaFuncSetAttribute(conv_res_kernel<1, true>,  cudaFuncAttributeMaxDynamicSharedMemorySize, SMEM_RES);
    cudaFuncSetAttribute(conv_s2_kernel,            cudaFuncAttributeMaxDynamicSharedMemorySize, SMEM_S2);
    cudaFuncSetAttribute(conv_tr_kernel,            cudaFuncAttributeMaxDynamicSharedMemorySize, SMEM_TR);
    cudaFuncSetAttribute(proj_kernel,               cudaFuncAttributeMaxDynamicSharedMemorySize, SMEM_PROJ);

    zero_loss_kernel<<<1, 1>>>();
    ne_kernel<<<2, 256>>>(codebook);

    float* h = A;
    float* t = Bb;

    // ---------- encoder ----------
    down0_kernel<<<2048, 256>>>(x, w_down0, b_down0, h);
    int T = 32768;
    for (int blk = 0; blk < 3; blk++) {
        if (blk > 0) {
            int Tout = T >> 1;
            conv_s2_kernel<<<NBATCH * (Tout >> 7), 256, SMEM_S2>>>(
                h, w_down + (size_t)(blk - 1) * 16384, b_down + (blk - 1) * 64, t, Tout);
            T = Tout;
            float* tmp = h; h = t; t = tmp;
        }
        for (int r = 0; r < 4; r++) {
            const float* w1 = w_res_e + (size_t)((blk * 4 + r) * 2 + 0) * 12288;
            const float* w2 = w_res_e + (size_t)((blk * 4 + r) * 2 + 1) * 12288;
            const float* bb1 = b_res_e + ((blk * 4 + r) * 2 + 0) * 64;
            const float* bb2 = b_res_e + ((blk * 4 + r) * 2 + 1) * 64;
            conv_res_kernel<3, false><<<NBATCH * (T >> 7), 256, SMEM_RES>>>(h, w1, bb1, nullptr, t, T);
            conv_res_kernel<1, true><<<NBATCH * (T >> 7), 256, SMEM_RES>>>(t, w2, bb2, h, h, T);
        }
    }

    // ---------- VQ (T = 8192) ----------
    vq_kernel<<<1024, 256>>>(h, codebook, t, out);
    loss_fin_kernel<<<1, 1>>>(out);
    { float* tmp = h; h = t; t = tmp; }   // h = z_q

    // ---------- decoder ----------
    for (int blk = 0; blk < 3; blk++) {
        for (int r = 0; r < 4; r++) {
            const float* w1 = w_res_d + (size_t)((blk * 4 + r) * 2 + 0) * 12288;
            const float* w2 = w_res_d + (size_t)((blk * 4 + r) * 2 + 1) * 12288;
            const float* bb1 = b_res_d + ((blk * 4 + r) * 2 + 0) * 64;
            const float* bb2 = b_res_d + ((blk * 4 + r) * 2 + 1) * 64;
            conv_res_kernel<1, false><<<NBATCH * (T >> 7), 256, SMEM_RES>>>(h, w1, bb1, nullptr, t, T);
            conv_res_kernel<3, true><<<NBATCH * (T >> 7), 256, SMEM_RES>>>(t, w2, bb2, h, h, T);
        }
        int Tout = T << 1;
        conv_tr_kernel<<<NBATCH * (Tout >> 8), 256, SMEM_TR>>>(
            h, w_up + (size_t)blk * 16384, b_up + blk * 64, t, Tout);
        T = Tout;
        float* tmp = h; h = t; t = tmp;
    }

    // ---------- projection (T = 65536) ----------
    proj_kernel<<<NBATCH * (T >> 8), 256, SMEM_PROJ>>>(h, w_proj, b_proj, out, T);
}

// round 4
// speedup vs baseline: 1.3105x; 1.3105x over previous
#include <cuda_runtime.h>
#include <math.h>

// ---------------- constants ----------------
#define NBATCH 4
#define TTOP   65536
#define OFF_XHAT 0
#define OFF_LOSS 262144
#define OFF_IDS  262145
#define OFF_SIM  294913
#define NEMB 512

#define ALIGN4(n) (((n) + 3) & ~3)

// ---------------- scratch ----------------
__device__ float g_A[16777216];
__device__ float g_B[16777216];
__device__ float g_ne[NEMB];
__device__ float g_rsne[NEMB];
__device__ float g_loss;

__global__ void zero_loss_kernel() { g_loss = 0.f; }

__global__ void ne_kernel(const float* __restrict__ cb) {
    int e = blockIdx.x * blockDim.x + threadIdx.x;
    if (e < NEMB) {
        float s = 0.f;
        #pragma unroll 8
        for (int ci = 0; ci < 64; ci++) { float v = cb[e * 64 + ci]; s += v * v; }
        g_ne[e] = s;
        g_rsne[e] = rsqrtf(s);
    }
}

__global__ void loss_fin_kernel(float* __restrict__ out) {
    out[OFF_LOSS] = 1.25f * g_loss / 32768.0f;
}

// ---------------- first conv: Cin=1 -> 64, K=4, stride 2, ReLU ----------------
__global__ void __launch_bounds__(256) down0_kernel(
    const float* __restrict__ x, const float* __restrict__ w,
    const float* __restrict__ bias, float* __restrict__ y)
{
    __shared__ float ws[256];
    __shared__ float bs[64];
    int tid = threadIdx.x;
    ws[tid] = w[tid];
    if (tid < 64) bs[tid] = bias[tid];
    __syncthreads();

    int g = blockIdx.x * 256 + tid;
    int q = g & 3;
    int rest = g >> 2;
    int ot = rest & 32767;
    int b = rest >> 15;

    float acc[16];
    #pragma unroll
    for (int c = 0; c < 16; c++) acc[c] = bs[q * 16 + c];
    #pragma unroll
    for (int k = 0; k < 4; k++) {
        int t = 2 * ot - 1 + k;
        float xv = (t >= 0 && t < TTOP) ? x[(size_t)b * TTOP + t] : 0.f;
        #pragma unroll
        for (int c = 0; c < 16; c++) acc[c] += xv * ws[k * 64 + q * 16 + c];
    }
    float* op = y + ((size_t)(b * 32768 + ot)) * 64 + q * 16;
    #pragma unroll
    for (int c4 = 0; c4 < 4; c4++) {
        float4 o;
        o.x = fmaxf(acc[c4 * 4 + 0], 0.f);
        o.y = fmaxf(acc[c4 * 4 + 1], 0.f);
        o.z = fmaxf(acc[c4 * 4 + 2], 0.f);
        o.w = fmaxf(acc[c4 * 4 + 3], 0.f);
        *(float4*)(op + c4 * 4) = o;
    }
}

// ---------------- residual conv: K=3, dil DIL, 64->64, ReLU, optional +res ----
// Tile = 2^LOGT time steps, block = TILE threads (8t x 8co per thread).
// All 3 weight taps resident in smem (one sync); x window held in registers.
template<int LOGT, int DIL, bool RES>
__global__ void __launch_bounds__(1 << LOGT, 1) conv_res_kernel(
    const float* __restrict__ x, const float* __restrict__ w,
    const float* __restrict__ bias, const float* __restrict__ res,
    float* __restrict__ y, int T)
{
    constexpr int TILE = 1 << LOGT;
    constexpr int NTHR = TILE;
    constexpr int ROWS = TILE + 2 * DIL;
    constexpr int W = 8 + 2 * DIL;

    extern __shared__ float smem[];
    float* xs = smem;                         // [ROWS][65]
    float* wsm = smem + ALIGN4(ROWS * 65);    // [3][64][64]

    const int tid = threadIdx.x;
    const int tilesPerB = T >> LOGT;
    const int b = blockIdx.x / tilesPerB;
    const int t0 = (blockIdx.x - b * tilesPerB) << LOGT;
    const float* xb = x + (size_t)b * T * 64;

    // stage x tile (coalesced float4 loads)
    for (int idx = tid; idx < ROWS * 16; idx += NTHR) {
        int r = idx >> 4, c4 = idx & 15;
        int gt = t0 - DIL + r;
        float4 v = make_float4(0.f, 0.f, 0.f, 0.f);
        if (gt >= 0 && gt < T) v = *(const float4*)(xb + (size_t)gt * 64 + c4 * 4);
        float* d = &xs[r * 65 + c4 * 4];
        d[0] = v.x; d[1] = v.y; d[2] = v.z; d[3] = v.w;
    }
    // stage all 3 weight taps once
    {
        const float4* wg = (const float4*)w;
        float4* wd = (float4*)wsm;
        for (int idx = tid; idx < 3072; idx += NTHR) wd[idx] = wg[idx];
    }
    __syncthreads();

    const int tg = tid >> 3;
    const int cg = tid & 7;
    const int tb = tg << 3;

    float acc[8][8];
    #pragma unroll
    for (int i = 0; i < 8; i++)
        #pragma unroll
        for (int j = 0; j < 8; j++) acc[i][j] = 0.f;

    const float* wrow = wsm + cg * 8;

    #pragma unroll 2
    for (int ci = 0; ci < 64; ci++) {
        // x window for all taps, read once
        float xw[W];
        #pragma unroll
        for (int m = 0; m < W; m++) xw[m] = xs[(tb + m) * 65 + ci];

        const float* wci = wrow + ci * 64;
        #pragma unroll
        for (int k = 0; k < 3; k++) {
            float4 wa = *(const float4*)(wci + k * 4096);
            float4 wb = *(const float4*)(wci + k * 4096 + 4);
            #pragma unroll
            for (int i = 0; i < 8; i++) {
                float xv = xw[i + k * DIL];
                acc[i][0] += xv * wa.x; acc[i][1] += xv * wa.y;
                acc[i][2] += xv * wa.z; acc[i][3] += xv * wa.w;
                acc[i][4] += xv * wb.x; acc[i][5] += xv * wb.y;
                acc[i][6] += xv * wb.z; acc[i][7] += xv * wb.w;
            }
        }
    }

    const int co0 = cg * 8;
    float4 bv0 = *(const float4*)(bias + co0);
    float4 bv1 = *(const float4*)(bias + co0 + 4);
    #pragma unroll
    for (int i = 0; i < 8; i++) {
        int gt = t0 + tb + i;
        float* op = y + ((size_t)b * T + gt) * 64 + co0;
        float4 o0, o1;
        o0.x = fmaxf(acc[i][0] + bv0.x, 0.f);
        o0.y = fmaxf(acc[i][1] + bv0.y, 0.f);
        o0.z = fmaxf(acc[i][2] + bv0.z, 0.f);
        o0.w = fmaxf(acc[i][3] + bv0.w, 0.f);
        o1.x = fmaxf(acc[i][4] + bv1.x, 0.f);
        o1.y = fmaxf(acc[i][5] + bv1.y, 0.f);
        o1.z = fmaxf(acc[i][6] + bv1.z, 0.f);
        o1.w = fmaxf(acc[i][7] + bv1.w, 0.f);
        if (RES) {
            const float* rp = res + ((size_t)b * T + gt) * 64 + co0;
            float4 r0 = *(const float4*)rp;
            float4 r1 = *(const float4*)(rp + 4);
            o0.x += r0.x; o0.y += r0.y; o0.z += r0.z; o0.w += r0.w;
            o1.x += r1.x; o1.y += r1.y; o1.z += r1.z; o1.w += r1.w;
        }
        *(float4*)op = o0;
        *(float4*)(op + 4) = o1;
    }
}

// ---------------- strided down conv: K=4, stride 2, 64->64, ReLU ----------------
__global__ void __launch_bounds__(256, 2) conv_s2_kernel(
    const float* __restrict__ x, const float* __restrict__ w,
    const float* __restrict__ bias, float* __restrict__ y, int Tout)
{
    extern __shared__ float smem[];
    float* xs = smem;                           // [258][65]
    float* wsm = smem + ALIGN4(258 * 65);       // [64][64]
    const int Tin = Tout << 1;
    const int tid = threadIdx.x;
    const int tilesPerB = Tout >> 7;
    const int b = blockIdx.x / tilesPerB;
    const int t0 = (blockIdx.x - b * tilesPerB) << 7;
    const float* xb = x + (size_t)b * Tin * 64;

    for (int idx = tid; idx < 258 * 16; idx += 256) {
        int r = idx >> 4, c4 = idx & 15;
        int gt = 2 * t0 - 1 + r;
        float4 v = make_float4(0.f, 0.f, 0.f, 0.f);
        if (gt >= 0 && gt < Tin) v = *(const float4*)(xb + (size_t)gt * 64 + c4 * 4);
        float* d = &xs[r * 65 + c4 * 4];
        d[0] = v.x; d[1] = v.y; d[2] = v.z; d[3] = v.w;
    }

    const int tg = tid >> 3;
    const int cg = tid & 7;
    float acc[4][8];
    #pragma unroll
    for (int i = 0; i < 4; i++)
        #pragma unroll
        for (int j = 0; j < 8; j++) acc[i][j] = 0.f;

    for (int k = 0; k < 4; k++) {
        __syncthreads();
        {
            const float4* wg = (const float4*)(w + k * 4096);
            float4* wd = (float4*)wsm;
            for (int idx = tid; idx < 1024; idx += 256) wd[idx] = wg[idx];
        }
        __syncthreads();
        const float4* ws4 = (const float4*)wsm;
        #pragma unroll 2
        for (int ci = 0; ci < 64; ci++) {
            float4 wa = ws4[ci * 16 + cg * 2];
            float4 wb = ws4[ci * 16 + cg * 2 + 1];
            #pragma unroll
            for (int i = 0; i < 4; i++) {
                float xv = xs[(2 * (tg * 4 + i) + k) * 65 + ci];
                acc[i][0] += xv * wa.x; acc[i][1] += xv * wa.y;
                acc[i][2] += xv * wa.z; acc[i][3] += xv * wa.w;
                acc[i][4] += xv * wb.x; acc[i][5] += xv * wb.y;
                acc[i][6] += xv * wb.z; acc[i][7] += xv * wb.w;
            }
        }
    }

    const int co0 = cg * 8;
    float4 bv0 = *(const float4*)(bias + co0);
    float4 bv1 = *(const float4*)(bias + co0 + 4);
    #pragma unroll
    for (int i = 0; i < 4; i++) {
        int gt = t0 + tg * 4 + i;
        float* op = y + ((size_t)b * Tout + gt) * 64 + co0;
        float4 o0, o1;
        o0.x = fmaxf(acc[i][0] + bv0.x, 0.f);
        o0.y = fmaxf(acc[i][1] + bv0.y, 0.f);
        o0.z = fmaxf(acc[i][2] + bv0.z, 0.f);
        o0.w = fmaxf(acc[i][3] + bv0.w, 0.f);
        o1.x = fmaxf(acc[i][4] + bv1.x, 0.f);
        o1.y = fmaxf(acc[i][5] + bv1.y, 0.f);
        o1.z = fmaxf(acc[i][6] + bv1.z, 0.f);
        o1.w = fmaxf(acc[i][7] + bv1.w, 0.f);
        *(float4*)op = o0;
        *(float4*)(op + 4) = o1;
    }
}

// ---------------- transposed conv: K=4, stride 2, 64->64, ReLU ----------------
__global__ void __launch_bounds__(256, 2) conv_tr_kernel(
    const float* __restrict__ x, const float* __restrict__ w,
    const float* __restrict__ bias, float* __restrict__ y, int Tout)
{
    extern __shared__ float smem[];
    float* xs = smem;                           // [130][65]
    float* wsm = smem + ALIGN4(130 * 65);       // [4][64][64]
    const int Tin = Tout >> 1;
    const int tid = threadIdx.x;
    const int tilesPerB = Tout >> 8;
    const int b = blockIdx.x / tilesPerB;
    const int t0 = (blockIdx.x - b * tilesPerB) << 8;
    const float* xb = x + (size_t)b * Tin * 64;
    const int in0 = (t0 >> 1) - 1;

    for (int idx = tid; idx < 130 * 16; idx += 256) {
        int r = idx >> 4, c4 = idx & 15;
        int gt = in0 + r;
        float4 v = make_float4(0.f, 0.f, 0.f, 0.f);
        if (gt >= 0 && gt < Tin) v = *(const float4*)(xb + (size_t)gt * 64 + c4 * 4);
        float* d = &xs[r * 65 + c4 * 4];
        d[0] = v.x; d[1] = v.y; d[2] = v.z; d[3] = v.w;
    }
    {
        const float4* wg = (const float4*)w;
        float4* wd = (float4*)wsm;
        for (int idx = tid; idx < 4096; idx += 256) wd[idx] = wg[idx];
    }
    __syncthreads();

    const int tg = tid >> 3;
    const int cg = tid & 7;
    float acc[8][8];
    #pragma unroll
    for (int i = 0; i < 8; i++)
        #pragma unroll
        for (int j = 0; j < 8; j++) acc[i][j] = 0.f;

    const float4* ws4 = (const float4*)wsm;
    #pragma unroll 2
    for (int ci = 0; ci < 64; ci++) {
        float xv[6];
        #pragma unroll
        for (int m = 0; m < 6; m++) xv[m] = xs[(tg * 4 + m) * 65 + ci];
        {
            float4 wa0 = ws4[ci * 16 + cg * 2];
            float4 wb0 = ws4[ci * 16 + cg * 2 + 1];
            float4 wa2 = ws4[2 * 1024 + ci * 16 + cg * 2];
            float4 wb2 = ws4[2 * 1024 + ci * 16 + cg * 2 + 1];
            #pragma unroll
            for (int ii = 0; ii < 4; ii++) {
                const int i = 2 * ii;
                float xa = xv[ii], xbv = xv[ii + 1];
                acc[i][0] += xa * wa0.x + xbv * wa2.x;
                acc[i][1] += xa * wa0.y + xbv * wa2.y;
                acc[i][2] += xa * wa0.z + xbv * wa2.z;
                acc[i][3] += xa * wa0.w + xbv * wa2.w;
                acc[i][4] += xa * wb0.x + xbv * wb2.x;
                acc[i][5] += xa * wb0.y + xbv * wb2.y;
                acc[i][6] += xa * wb0.z + xbv * wb2.z;
                acc[i][7] += xa * wb0.w + xbv * wb2.w;
            }
        }
        {
            float4 wa1 = ws4[1024 + ci * 16 + cg * 2];
            float4 wb1 = ws4[1024 + ci * 16 + cg * 2 + 1];
            float4 wa3 = ws4[3 * 1024 + ci * 16 + cg * 2];
            float4 wb3 = ws4[3 * 1024 + ci * 16 + cg * 2 + 1];
            #pragma unroll
            for (int ii = 0; ii < 4; ii++) {
                const int i = 2 * ii + 1;
                float xa = xv[ii + 1], xbv = xv[ii + 2];
                acc[i][0] += xa * wa1.x + xbv * wa3.x;
                acc[i][1] += xa * wa1.y + xbv * wa3.y;
                acc[i][2] += xa * wa1.z + xbv * wa3.z;
                acc[i][3] += xa * wa1.w + xbv * wa3.w;
                acc[i][4] += xa * wb1.x + xbv * wb3.x;
                acc[i][5] += xa * wb1.y + xbv * wb3.y;
                acc[i][6] += xa * wb1.z + xbv * wb3.z;
                acc[i][7] += xa * wb1.w + xbv * wb3.w;
            }
        }
    }

    const int co0 = cg * 8;
    float4 bv0 = *(const float4*)(bias + co0);
    float4 bv1 = *(const float4*)(bias + co0 + 4);
    #pragma unroll
    for (int i = 0; i < 8; i++) {
        int gt = t0 + tg * 8 + i;
        float* op = y + ((size_t)b * Tout + gt) * 64 + co0;
        float4 o0, o1;
        o0.x = fmaxf(acc[i][0] + bv0.x, 0.f);
        o0.y = fmaxf(acc[i][1] + bv0.y, 0.f);
        o0.z = fmaxf(acc[i][2] + bv0.z, 0.f);
        o0.w = fmaxf(acc[i][3] + bv0.w, 0.f);
        o1.x = fmaxf(acc[i][4] + bv1.x, 0.f);
        o1.y = fmaxf(acc[i][5] + bv1.y, 0.f);
        o1.z = fmaxf(acc[i][6] + bv1.z, 0.f);
        o1.w = fmaxf(acc[i][7] + bv1.w, 0.f);
        *(float4*)op = o0;
        *(float4*)(op + 4) = o1;
    }
}

// ---------------- final projection: K=3, dil 1, 64->1, linear ----------------
__global__ void __launch_bounds__(256) proj_kernel(
    const float* __restrict__ x, const float* __restrict__ w,
    const float* __restrict__ bias, float* __restrict__ out, int T)
{
    extern __shared__ float smem[];
    float* xs = smem;                           // [258][65]
    float* ws = smem + ALIGN4(258 * 65);        // [192]
    const int tid = threadIdx.x;
    const int tilesPerB = T >> 8;
    const int b = blockIdx.x / tilesPerB;
    const int t0 = (blockIdx.x - b * tilesPerB) << 8;
    const float* xb = x + (size_t)b * T * 64;

    for (int idx = tid; idx < 258 * 16; idx += 256) {
        int r = idx >> 4, c4 = idx & 15;
        int gt = t0 - 1 + r;
        float4 v = make_float4(0.f, 0.f, 0.f, 0.f);
        if (gt >= 0 && gt < T) v = *(const float4*)(xb + (size_t)gt * 64 + c4 * 4);
        float* d = &xs[r * 65 + c4 * 4];
        d[0] = v.x; d[1] = v.y; d[2] = v.z; d[3] = v.w;
    }
    if (tid < 192) ws[tid] = w[tid];
    __syncthreads();

    float acc = 0.f;
    #pragma unroll
    for (int k = 0; k < 3; k++) {
        #pragma unroll 8
        for (int ci = 0; ci < 64; ci++)
            acc += xs[(tid + k) * 65 + ci] * ws[k * 64 + ci];
    }
    out[OFF_XHAT + (size_t)b * T + t0 + tid] = acc + bias[0];
}

// ---------------- VQ ----------------
__global__ void __launch_bounds__(256) vq_kernel(
    const float* __restrict__ ze, const float* __restrict__ cb,
    float* __restrict__ zq, float* __restrict__ dout)
{
    __shared__ float zs[32 * 65];
    __shared__ float cbs[128 * 65];
    __shared__ float nzs[32], rsnzs[32];

    const int tid = threadIdx.x;
    const int rg = tid >> 5;
    const int eg = tid & 31;
    const int row0 = blockIdx.x * 32;

    for (int idx = tid; idx < 32 * 16; idx += 256) {
        int r = idx >> 4, c4 = idx & 15;
        float4 v = *(const float4*)(ze + (size_t)(row0 + r) * 64 + c4 * 4);
        float* d = &zs[r * 65 + c4 * 4];
        d[0] = v.x; d[1] = v.y; d[2] = v.z; d[3] = v.w;
    }
    __syncthreads();
    if (tid < 32) {
        float s = 0.f;
        #pragma unroll 8
        for (int ci = 0; ci < 64; ci++) { float v = zs[tid * 65 + ci]; s += v * v; }
        nzs[tid] = s;
        rsnzs[tid] = rsqrtf(s);
    }

    float bv[4] = {3.4e38f, 3.4e38f, 3.4e38f, 3.4e38f};
    int bi[4] = {0, 0, 0, 0};

    for (int c = 0; c < 4; c++) {
        __syncthreads();
        for (int idx = tid; idx < 128 * 16; idx += 256) {
            int e = idx >> 4, c4 = idx & 15;
            float4 v = *(const float4*)(cb + (size_t)(c * 128 + e) * 64 + c4 * 4);
            float* d = &cbs[e * 65 + c4 * 4];
            d[0] = v.x; d[1] = v.y; d[2] = v.z; d[3] = v.w;
        }
        __syncthreads();

        float acc[4][4];
        #pragma unroll
        for (int i = 0; i < 4; i++)
            #pragma unroll
            for (int j = 0; j < 4; j++) acc[i][j] = 0.f;

        #pragma unroll 4
        for (int ci = 0; ci < 64; ci++) {
            float zv[4], cv[4];
            #pragma unroll
            for (int i = 0; i < 4; i++) zv[i] = zs[(rg * 4 + i) * 65 + ci];
            #pragma unroll
            for (int j = 0; j < 4; j++) cv[j] = cbs[(j * 32 + eg) * 65 + ci];
            #pragma unroll
            for (int i = 0; i < 4; i++)
                #pragma unroll
                for (int j = 0; j < 4; j++) acc[i][j] += zv[i] * cv[j];
        }

        #pragma unroll
        for (int j = 0; j < 4; j++) {
            int e = c * 128 + j * 32 + eg;
            float nev = __ldg(&g_ne[e]);
            float rse = __ldg(&g_rsne[e]);
            #pragma unroll
            for (int i = 0; i < 4; i++) {
                int r = rg * 4 + i;
                float dot = acc[i][j];
                float dist = -2.0f * dot + nzs[r] + nev;
                float sim = dot * rsnzs[r] * rse;
                dout[OFF_SIM + (size_t)(row0 + r) * NEMB + e] = sim;
                if (dist < bv[i]) { bv[i] = dist; bi[i] = e; }
            }
        }
    }

    #pragma unroll
    for (int i = 0; i < 4; i++) {
        float v = bv[i];
        int idx = bi[i];
        #pragma unroll
        for (int off = 16; off > 0; off >>= 1) {
            float ov = __shfl_down_sync(0xffffffffu, v, off);
            int oi = __shfl_down_sync(0xffffffffu, idx, off);
            if (ov < v || (ov == v && oi < idx)) { v = ov; idx = oi; }
        }
        if (eg == 0) {
            int r = rg * 4 + i;
            int gr = row0 + r;
            dout[OFF_IDS + gr] = (float)idx;
            float s = 0.f;
            const float* cp = cb + (size_t)idx * 64;
            float* qp = zq + (size_t)gr * 64;
            #pragma unroll 8
            for (int ci = 0; ci < 64; ci++) {
                float cvv = __ldg(cp + ci);
                qp[ci] = cvv;
                float d = zs[r * 65 + ci] - cvv;
                s += d * d;
            }
            atomicAdd(&g_loss, sqrtf(s));
        }
    }
}

// ---------------- host orchestration ----------------
#define SMEM_RES(LOGT, DIL) ((ALIGN4(((1 << (LOGT)) + 2 * (DIL)) * 65) + 3 * 4096) * 4)
#define SMEM_S2   ((ALIGN4(258 * 65) + 4096) * 4)
#define SMEM_TR   ((ALIGN4(130 * 65) + 16384) * 4)
#define SMEM_PROJ ((ALIGN4(258 * 65) + 192) * 4)

static inline void launch_res_pair(bool enc, int T,
    const float* w1, const float* b1, const float* w2, const float* b2,
    float* h, float* t)
{
    // encoder: conv(dil3) then conv(dil1)+res ; decoder: conv(dil1) then conv(dil3)+res
    if (T >= 16384) {
        const int grid = NBATCH * (T >> 9);
        if (enc) {
            conv_res_kernel<9, 3, false><<<grid, 512, SMEM_RES(9, 3)>>>(h, w1, b1, nullptr, t, T);
            conv_res_kernel<9, 1, true ><<<grid, 512, SMEM_RES(9, 1)>>>(t, w2, b2, h, h, T);
        } else {
            conv_res_kernel<9, 1, false><<<grid, 512, SMEM_RES(9, 1)>>>(h, w1, b1, nullptr, t, T);
            conv_res_kernel<9, 3, true ><<<grid, 512, SMEM_RES(9, 3)>>>(t, w2, b2, h, h, T);
        }
    } else {
        const int grid = NBATCH * (T >> 8);
        if (enc) {
            conv_res_kernel<8, 3, false><<<grid, 256, SMEM_RES(8, 3)>>>(h, w1, b1, nullptr, t, T);
            conv_res_kernel<8, 1, true ><<<grid, 256, SMEM_RES(8, 1)>>>(t, w2, b2, h, h, T);
        } else {
            conv_res_kernel<8, 1, false><<<grid, 256, SMEM_RES(8, 1)>>>(h, w1, b1, nullptr, t, T);
            conv_res_kernel<8, 3, true ><<<grid, 256, SMEM_RES(8, 3)>>>(t, w2, b2, h, h, T);
        }
    }
}

extern "C" void kernel_launch(void* const* d_in, const int* in_sizes, int n_in,
                              void* d_out, int out_size)
{
    const float* x        = (const float*)d_in[0];
    const float* w_down0  = (const float*)d_in[1];
    const float* b_down0  = (const float*)d_in[2];
    const float* w_down   = (const float*)d_in[3];
    const float* b_down   = (const float*)d_in[4];
    const float* w_res_e  = (const float*)d_in[5];
    const float* b_res_e  = (const float*)d_in[6];
    const float* codebook = (const float*)d_in[7];
    const float* w_res_d  = (const float*)d_in[8];
    const float* b_res_d  = (const float*)d_in[9];
    const float* w_up     = (const float*)d_in[10];
    const float* b_up     = (const float*)d_in[11];
    const float* w_proj   = (const float*)d_in[12];
    const float* b_proj   = (const float*)d_in[13];
    float* out = (float*)d_out;

    float *A, *Bb;
    cudaGetSymbolAddress((void**)&A, g_A);
    cudaGetSymbolAddress((void**)&Bb, g_B);

    cudaFuncSetAttribute(conv_res_kernel<9, 3, false>, cudaFuncAttributeMaxDynamicSharedMemorySize, SMEM_RES(9, 3));
    cudaFuncSetAttribute(conv_res_kernel<9, 3, true >, cudaFuncAttributeMaxDynamicSharedMemorySize, SMEM_RES(9, 3));
    cudaFuncSetAttribute(conv_res_kernel<9, 1, false>, cudaFuncAttributeMaxDynamicSharedMemorySize, SMEM_RES(9, 1));
    cudaFuncSetAttribute(conv_res_kernel<9, 1, true >, cudaFuncAttributeMaxDynamicSharedMemorySize, SMEM_RES(9, 1));
    cudaFuncSetAttribute(conv_res_kernel<8, 3, false>, cudaFuncAttributeMaxDynamicSharedMemorySize, SMEM_RES(8, 3));
    cudaFuncSetAttribute(conv_res_kernel<8, 3, true >, cudaFuncAttributeMaxDynamicSharedMemorySize, SMEM_RES(8, 3));
    cudaFuncSetAttribute(conv_res_kernel<8, 1, false>, cudaFuncAttributeMaxDynamicSharedMemorySize, SMEM_RES(8, 1));
    cudaFuncSetAttribute(conv_res_kernel<8, 1, true >, cudaFuncAttributeMaxDynamicSharedMemorySize, SMEM_RES(8, 1));
    cudaFuncSetAttribute(conv_s2_kernel, cudaFuncAttributeMaxDynamicSharedMemorySize, SMEM_S2);
    cudaFuncSetAttribute(conv_tr_kernel, cudaFuncAttributeMaxDynamicSharedMemorySize, SMEM_TR);
    cudaFuncSetAttribute(proj_kernel,    cudaFuncAttributeMaxDynamicSharedMemorySize, SMEM_PROJ);

    zero_loss_kernel<<<1, 1>>>();
    ne_kernel<<<2, 256>>>(codebook);

    float* h = A;
    float* t = Bb;

    // ---------- encoder ----------
    down0_kernel<<<2048, 256>>>(x, w_down0, b_down0, h);
    int T = 32768;
    for (int blk = 0; blk < 3; blk++) {
        if (blk > 0) {
            int Tout = T >> 1;
            conv_s2_kernel<<<NBATCH * (Tout >> 7), 256, SMEM_S2>>>(
                h, w_down + (size_t)(blk - 1) * 16384, b_down + (blk - 1) * 64, t, Tout);
            T = Tout;
            float* tmp = h; h = t; t = tmp;
        }
        for (int r = 0; r < 4; r++) {
            const float* w1 = w_res_e + (size_t)((blk * 4 + r) * 2 + 0) * 12288;
            const float* w2 = w_res_e + (size_t)((blk * 4 + r) * 2 + 1) * 12288;
            const float* bb1 = b_res_e + ((blk * 4 + r) * 2 + 0) * 64;
            const float* bb2 = b_res_e + ((blk * 4 + r) * 2 + 1) * 64;
            launch_res_pair(true, T, w1, bb1, w2, bb2, h, t);
        }
    }

    // ---------- VQ (T = 8192) ----------
    vq_kernel<<<1024, 256>>>(h, codebook, t, out);
    loss_fin_kernel<<<1, 1>>>(out);
    { float* tmp = h; h = t; t = tmp; }   // h = z_q

    // ---------- decoder ----------
    for (int blk = 0; blk < 3; blk++) {
        for (int r = 0; r < 4; r++) {
            const float* w1 = w_res_d + (size_t)((blk * 4 + r) * 2 + 0) * 12288;
            const float* w2 = w_res_d + (size_t)((blk * 4 + r) * 2 + 1) * 12288;
            const float* bb1 = b_res_d + ((blk * 4 + r) * 2 + 0) * 64;
            const float* bb2 = b_res_d + ((blk * 4 + r) * 2 + 1) * 64;
            launch_res_pair(false, T, w1, bb1, w2, bb2, h, t);
        }
        int Tout = T << 1;
        conv_tr_kernel<<<NBATCH * (Tout >> 8), 256, SMEM_TR>>>(
            h, w_up + (size_t)blk * 16384, b_up + blk * 64, t, Tout);
        T = Tout;
        float* tmp = h; h = t; t = tmp;
    }

    // ---------- projection (T = 65536) ----------
    proj_kernel<<<NBATCH * (T >> 8), 256, SMEM_PROJ>>>(h, w_proj, b_proj, out, T);
}

// round 5
// speedup vs baseline: 1.4121x; 1.0775x over previous
#include <cuda_runtime.h>
#include <math.h>

// ---------------- constants ----------------
#define NBATCH 4
#define TTOP   65536
#define OFF_XHAT 0
#define OFF_LOSS 262144
#define OFF_IDS  262145
#define OFF_SIM  294913
#define NEMB 512

#define ALIGN4(n) (((n) + 3) & ~3)

// ---------------- scratch ----------------
__device__ float g_A[16777216];
__device__ float g_B[16777216];
__device__ float g_ne[NEMB];
__device__ float g_rsne[NEMB];
__device__ float g_loss;

__global__ void zero_loss_kernel() { g_loss = 0.f; }

__global__ void ne_kernel(const float* __restrict__ cb) {
    int e = blockIdx.x * blockDim.x + threadIdx.x;
    if (e < NEMB) {
        float s = 0.f;
        #pragma unroll 8
        for (int ci = 0; ci < 64; ci++) { float v = cb[e * 64 + ci]; s += v * v; }
        g_ne[e] = s;
        g_rsne[e] = rsqrtf(s);
    }
}

__global__ void loss_fin_kernel(float* __restrict__ out) {
    out[OFF_LOSS] = 1.25f * g_loss / 32768.0f;
}

// ---------------- first conv: Cin=1 -> 64, K=4, stride 2, ReLU ----------------
__global__ void __launch_bounds__(256) down0_kernel(
    const float* __restrict__ x, const float* __restrict__ w,
    const float* __restrict__ bias, float* __restrict__ y)
{
    __shared__ float ws[256];
    __shared__ float bs[64];
    int tid = threadIdx.x;
    ws[tid] = w[tid];
    if (tid < 64) bs[tid] = bias[tid];
    __syncthreads();

    int g = blockIdx.x * 256 + tid;
    int q = g & 3;
    int rest = g >> 2;
    int ot = rest & 32767;
    int b = rest >> 15;

    float acc[16];
    #pragma unroll
    for (int c = 0; c < 16; c++) acc[c] = bs[q * 16 + c];
    #pragma unroll
    for (int k = 0; k < 4; k++) {
        int t = 2 * ot - 1 + k;
        float xv = (t >= 0 && t < TTOP) ? x[(size_t)b * TTOP + t] : 0.f;
        #pragma unroll
        for (int c = 0; c < 16; c++) acc[c] += xv * ws[k * 64 + q * 16 + c];
    }
    float* op = y + ((size_t)(b * 32768 + ot)) * 64 + q * 16;
    #pragma unroll
    for (int c4 = 0; c4 < 4; c4++) {
        float4 o;
        o.x = fmaxf(acc[c4 * 4 + 0], 0.f);
        o.y = fmaxf(acc[c4 * 4 + 1], 0.f);
        o.z = fmaxf(acc[c4 * 4 + 2], 0.f);
        o.w = fmaxf(acc[c4 * 4 + 3], 0.f);
        *(float4*)(op + c4 * 4) = o;
    }
}

// ---------------- residual conv: K=3, dil DIL, 64->64, ReLU, optional +res ----
// 128-t tile, 256 threads, 8t x 4co per thread. x in smem; weights streamed
// via __ldg (L1-resident, shared across CTAs). 3 CTAs/SM -> 24 warps.
template<int DIL, bool RES>
__global__ void __launch_bounds__(256, 3) conv_res_kernel(
    const float* __restrict__ x, const float* __restrict__ w,
    const float* __restrict__ bias, const float* __restrict__ res,
    float* __restrict__ y, int T)
{
    constexpr int TILE = 128;
    constexpr int ROWS = TILE + 2 * DIL;
    constexpr int W = 8 + 2 * DIL;

    extern __shared__ float smem[];
    float* xs = smem;   // [ROWS][65]

    const int tid = threadIdx.x;
    const int tilesPerB = T >> 7;
    const int b = blockIdx.x / tilesPerB;
    const int t0 = (blockIdx.x - b * tilesPerB) << 7;
    const float* xb = x + (size_t)b * T * 64;

    // stage x tile (coalesced float4 loads)
    for (int idx = tid; idx < ROWS * 16; idx += 256) {
        int r = idx >> 4, c4 = idx & 15;
        int gt = t0 - DIL + r;
        float4 v = make_float4(0.f, 0.f, 0.f, 0.f);
        if (gt >= 0 && gt < T) v = *(const float4*)(xb + (size_t)gt * 64 + c4 * 4);
        float* d = &xs[r * 65 + c4 * 4];
        d[0] = v.x; d[1] = v.y; d[2] = v.z; d[3] = v.w;
    }
    __syncthreads();

    const int tg = tid >> 4;        // 16 time groups of 8
    const int cg = tid & 15;        // 16 co groups of 4
    const int tb = tg << 3;
    const int co0 = cg << 2;

    float acc[8][4];
    #pragma unroll
    for (int i = 0; i < 8; i++)
        #pragma unroll
        for (int j = 0; j < 4; j++) acc[i][j] = 0.f;

    const float4* wg = (const float4*)(w + co0);   // stride 16 float4 per ci

    #pragma unroll 2
    for (int ci = 0; ci < 64; ci++) {
        float xw[W];
        #pragma unroll
        for (int m = 0; m < W; m++) xw[m] = xs[(tb + m) * 65 + ci];

        #pragma unroll
        for (int k = 0; k < 3; k++) {
            float4 wa = __ldg(wg + (k * 4096 + ci * 64) / 4);
            #pragma unroll
            for (int i = 0; i < 8; i++) {
                float xv = xw[i + k * DIL];
                acc[i][0] += xv * wa.x; acc[i][1] += xv * wa.y;
                acc[i][2] += xv * wa.z; acc[i][3] += xv * wa.w;
            }
        }
    }

    float4 bv = *(const float4*)(bias + co0);
    #pragma unroll
    for (int i = 0; i < 8; i++) {
        int gt = t0 + tb + i;
        float* op = y + ((size_t)b * T + gt) * 64 + co0;
        float4 o;
        o.x = fmaxf(acc[i][0] + bv.x, 0.f);
        o.y = fmaxf(acc[i][1] + bv.y, 0.f);
        o.z = fmaxf(acc[i][2] + bv.z, 0.f);
        o.w = fmaxf(acc[i][3] + bv.w, 0.f);
        if (RES) {
            float4 r0 = *(const float4*)(res + ((size_t)b * T + gt) * 64 + co0);
            o.x += r0.x; o.y += r0.y; o.z += r0.z; o.w += r0.w;
        }
        *(float4*)op = o;
    }
}

// ---------------- strided down conv: K=4, stride 2, 64->64, ReLU ----------------
__global__ void __launch_bounds__(256, 2) conv_s2_kernel(
    const float* __restrict__ x, const float* __restrict__ w,
    const float* __restrict__ bias, float* __restrict__ y, int Tout)
{
    extern __shared__ float smem[];
    float* xs = smem;                           // [258][65]
    float* wsm = smem + ALIGN4(258 * 65);       // [64][64]
    const int Tin = Tout << 1;
    const int tid = threadIdx.x;
    const int tilesPerB = Tout >> 7;
    const int b = blockIdx.x / tilesPerB;
    const int t0 = (blockIdx.x - b * tilesPerB) << 7;
    const float* xb = x + (size_t)b * Tin * 64;

    for (int idx = tid; idx < 258 * 16; idx += 256) {
        int r = idx >> 4, c4 = idx & 15;
        int gt = 2 * t0 - 1 + r;
        float4 v = make_float4(0.f, 0.f, 0.f, 0.f);
        if (gt >= 0 && gt < Tin) v = *(const float4*)(xb + (size_t)gt * 64 + c4 * 4);
        float* d = &xs[r * 65 + c4 * 4];
        d[0] = v.x; d[1] = v.y; d[2] = v.z; d[3] = v.w;
    }

    const int tg = tid >> 3;
    const int cg = tid & 7;
    float acc[4][8];
    #pragma unroll
    for (int i = 0; i < 4; i++)
        #pragma unroll
        for (int j = 0; j < 8; j++) acc[i][j] = 0.f;

    for (int k = 0; k < 4; k++) {
        __syncthreads();
        {
            const float4* wg = (const float4*)(w + k * 4096);
            float4* wd = (float4*)wsm;
            for (int idx = tid; idx < 1024; idx += 256) wd[idx] = wg[idx];
        }
        __syncthreads();
        const float4* ws4 = (const float4*)wsm;
        #pragma unroll 2
        for (int ci = 0; ci < 64; ci++) {
            float4 wa = ws4[ci * 16 + cg * 2];
            float4 wb = ws4[ci * 16 + cg * 2 + 1];
            #pragma unroll
            for (int i = 0; i < 4; i++) {
                float xv = xs[(2 * (tg * 4 + i) + k) * 65 + ci];
                acc[i][0] += xv * wa.x; acc[i][1] += xv * wa.y;
                acc[i][2] += xv * wa.z; acc[i][3] += xv * wa.w;
                acc[i][4] += xv * wb.x; acc[i][5] += xv * wb.y;
                acc[i][6] += xv * wb.z; acc[i][7] += xv * wb.w;
            }
        }
    }

    const int co0 = cg * 8;
    float4 bv0 = *(const float4*)(bias + co0);
    float4 bv1 = *(const float4*)(bias + co0 + 4);
    #pragma unroll
    for (int i = 0; i < 4; i++) {
        int gt = t0 + tg * 4 + i;
        float* op = y + ((size_t)b * Tout + gt) * 64 + co0;
        float4 o0, o1;
        o0.x = fmaxf(acc[i][0] + bv0.x, 0.f);
        o0.y = fmaxf(acc[i][1] + bv0.y, 0.f);
        o0.z = fmaxf(acc[i][2] + bv0.z, 0.f);
        o0.w = fmaxf(acc[i][3] + bv0.w, 0.f);
        o1.x = fmaxf(acc[i][4] + bv1.x, 0.f);
        o1.y = fmaxf(acc[i][5] + bv1.y, 0.f);
        o1.z = fmaxf(acc[i][6] + bv1.z, 0.f);
        o1.w = fmaxf(acc[i][7] + bv1.w, 0.f);
        *(float4*)op = o0;
        *(float4*)(op + 4) = o1;
    }
}

// ---------------- transposed conv: K=4, stride 2, 64->64, ReLU ----------------
__global__ void __launch_bounds__(256, 2) conv_tr_kernel(
    const float* __restrict__ x, const float* __restrict__ w,
    const float* __restrict__ bias, float* __restrict__ y, int Tout)
{
    extern __shared__ float smem[];
    float* xs = smem;                           // [130][65]
    float* wsm = smem + ALIGN4(130 * 65);       // [4][64][64]
    const int Tin = Tout >> 1;
    const int tid = threadIdx.x;
    const int tilesPerB = Tout >> 8;
    const int b = blockIdx.x / tilesPerB;
    const int t0 = (blockIdx.x - b * tilesPerB) << 8;
    const float* xb = x + (size_t)b * Tin * 64;
    const int in0 = (t0 >> 1) - 1;

    for (int idx = tid; idx < 130 * 16; idx += 256) {
        int r = idx >> 4, c4 = idx & 15;
        int gt = in0 + r;
        float4 v = make_float4(0.f, 0.f, 0.f, 0.f);
        if (gt >= 0 && gt < Tin) v = *(const float4*)(xb + (size_t)gt * 64 + c4 * 4);
        float* d = &xs[r * 65 + c4 * 4];
        d[0] = v.x; d[1] = v.y; d[2] = v.z; d[3] = v.w;
    }
    {
        const float4* wg = (const float4*)w;
        float4* wd = (float4*)wsm;
        for (int idx = tid; idx < 4096; idx += 256) wd[idx] = wg[idx];
    }
    __syncthreads();

    const int tg = tid >> 3;
    const int cg = tid & 7;
    float acc[8][8];
    #pragma unroll
    for (int i = 0; i < 8; i++)
        #pragma unroll
        for (int j = 0; j < 8; j++) acc[i][j] = 0.f;

    const float4* ws4 = (const float4*)wsm;
    #pragma unroll 2
    for (int ci = 0; ci < 64; ci++) {
        float xv[6];
        #pragma unroll
        for (int m = 0; m < 6; m++) xv[m] = xs[(tg * 4 + m) * 65 + ci];
        {
            float4 wa0 = ws4[ci * 16 + cg * 2];
            float4 wb0 = ws4[ci * 16 + cg * 2 + 1];
            float4 wa2 = ws4[2 * 1024 + ci * 16 + cg * 2];
            float4 wb2 = ws4[2 * 1024 + ci * 16 + cg * 2 + 1];
            #pragma unroll
            for (int ii = 0; ii < 4; ii++) {
                const int i = 2 * ii;
                float xa = xv[ii], xbv = xv[ii + 1];
                acc[i][0] += xa * wa0.x + xbv * wa2.x;
                acc[i][1] += xa * wa0.y + xbv * wa2.y;
                acc[i][2] += xa * wa0.z + xbv * wa2.z;
                acc[i][3] += xa * wa0.w + xbv * wa2.w;
                acc[i][4] += xa * wb0.x + xbv * wb2.x;
                acc[i][5] += xa * wb0.y + xbv * wb2.y;
                acc[i][6] += xa * wb0.z + xbv * wb2.z;
                acc[i][7] += xa * wb0.w + xbv * wb2.w;
            }
        }
        {
            float4 wa1 = ws4[1024 + ci * 16 + cg * 2];
            float4 wb1 = ws4[1024 + ci * 16 + cg * 2 + 1];
            float4 wa3 = ws4[3 * 1024 + ci * 16 + cg * 2];
            float4 wb3 = ws4[3 * 1024 + ci * 16 + cg * 2 + 1];
            #pragma unroll
            for (int ii = 0; ii < 4; ii++) {
                const int i = 2 * ii + 1;
                float xa = xv[ii + 1], xbv = xv[ii + 2];
                acc[i][0] += xa * wa1.x + xbv * wa3.x;
                acc[i][1] += xa * wa1.y + xbv * wa3.y;
                acc[i][2] += xa * wa1.z + xbv * wa3.z;
                acc[i][3] += xa * wa1.w + xbv * wa3.w;
                acc[i][4] += xa * wb1.x + xbv * wb3.x;
                acc[i][5] += xa * wb1.y + xbv * wb3.y;
                acc[i][6] += xa * wb1.z + xbv * wb3.z;
                acc[i][7] += xa * wb1.w + xbv * wb3.w;
            }
        }
    }

    const int co0 = cg * 8;
    float4 bv0 = *(const float4*)(bias + co0);
    float4 bv1 = *(const float4*)(bias + co0 + 4);
    #pragma unroll
    for (int i = 0; i < 8; i++) {
        int gt = t0 + tg * 8 + i;
        float* op = y + ((size_t)b * Tout + gt) * 64 + co0;
        float4 o0, o1;
        o0.x = fmaxf(acc[i][0] + bv0.x, 0.f);
        o0.y = fmaxf(acc[i][1] + bv0.y, 0.f);
        o0.z = fmaxf(acc[i][2] + bv0.z, 0.f);
        o0.w = fmaxf(acc[i][3] + bv0.w, 0.f);
        o1.x = fmaxf(acc[i][4] + bv1.x, 0.f);
        o1.y = fmaxf(acc[i][5] + bv1.y, 0.f);
        o1.z = fmaxf(acc[i][6] + bv1.z, 0.f);
        o1.w = fmaxf(acc[i][7] + bv1.w, 0.f);
        *(float4*)op = o0;
        *(float4*)(op + 4) = o1;
    }
}

// ---------------- final projection: K=3, dil 1, 64->1, linear ----------------
__global__ void __launch_bounds__(256) proj_kernel(
    const float* __restrict__ x, const float* __restrict__ w,
    const float* __restrict__ bias, float* __restrict__ out, int T)
{
    extern __shared__ float smem[];
    float* xs = smem;                           // [258][65]
    float* ws = smem + ALIGN4(258 * 65);        // [192]
    const int tid = threadIdx.x;
    const int tilesPerB = T >> 8;
    const int b = blockIdx.x / tilesPerB;
    const int t0 = (blockIdx.x - b * tilesPerB) << 8;
    const float* xb = x + (size_t)b * T * 64;

    for (int idx = tid; idx < 258 * 16; idx += 256) {
        int r = idx >> 4, c4 = idx & 15;
        int gt = t0 - 1 + r;
        float4 v = make_float4(0.f, 0.f, 0.f, 0.f);
        if (gt >= 0 && gt < T) v = *(const float4*)(xb + (size_t)gt * 64 + c4 * 4);
        float* d = &xs[r * 65 + c4 * 4];
        d[0] = v.x; d[1] = v.y; d[2] = v.z; d[3] = v.w;
    }
    if (tid < 192) ws[tid] = w[tid];
    __syncthreads();

    float acc = 0.f;
    #pragma unroll
    for (int k = 0; k < 3; k++) {
        #pragma unroll 8
        for (int ci = 0; ci < 64; ci++)
            acc += xs[(tid + k) * 65 + ci] * ws[k * 64 + ci];
    }
    out[OFF_XHAT + (size_t)b * T + t0 + tid] = acc + bias[0];
}

// ---------------- VQ ----------------
__global__ void __launch_bounds__(256) vq_kernel(
    const float* __restrict__ ze, const float* __restrict__ cb,
    float* __restrict__ zq, float* __restrict__ dout)
{
    __shared__ float zs[32 * 65];
    __shared__ float cbs[128 * 65];
    __shared__ float nzs[32], rsnzs[32];

    const int tid = threadIdx.x;
    const int rg = tid >> 5;
    const int eg = tid & 31;
    const int row0 = blockIdx.x * 32;

    for (int idx = tid; idx < 32 * 16; idx += 256) {
        int r = idx >> 4, c4 = idx & 15;
        float4 v = *(const float4*)(ze + (size_t)(row0 + r) * 64 + c4 * 4);
        float* d = &zs[r * 65 + c4 * 4];
        d[0] = v.x; d[1] = v.y; d[2] = v.z; d[3] = v.w;
    }
    __syncthreads();
    if (tid < 32) {
        float s = 0.f;
        #pragma unroll 8
        for (int ci = 0; ci < 64; ci++) { float v = zs[tid * 65 + ci]; s += v * v; }
        nzs[tid] = s;
        rsnzs[tid] = rsqrtf(s);
    }

    float bv[4] = {3.4e38f, 3.4e38f, 3.4e38f, 3.4e38f};
    int bi[4] = {0, 0, 0, 0};

    for (int c = 0; c < 4; c++) {
        __syncthreads();
        for (int idx = tid; idx < 128 * 16; idx += 256) {
            int e = idx >> 4, c4 = idx & 15;
            float4 v = *(const float4*)(cb + (size_t)(c * 128 + e) * 64 + c4 * 4);
            float* d = &cbs[e * 65 + c4 * 4];
            d[0] = v.x; d[1] = v.y; d[2] = v.z; d[3] = v.w;
        }
        __syncthreads();

        float acc[4][4];
        #pragma unroll
        for (int i = 0; i < 4; i++)
            #pragma unroll
            for (int j = 0; j < 4; j++) acc[i][j] = 0.f;

        #pragma unroll 4
        for (int ci = 0; ci < 64; ci++) {
            float zv[4], cv[4];
            #pragma unroll
            for (int i = 0; i < 4; i++) zv[i] = zs[(rg * 4 + i) * 65 + ci];
            #pragma unroll
            for (int j = 0; j < 4; j++) cv[j] = cbs[(j * 32 + eg) * 65 + ci];
            #pragma unroll
            for (int i = 0; i < 4; i++)
                #pragma unroll
                for (int j = 0; j < 4; j++) acc[i][j] += zv[i] * cv[j];
        }

        #pragma unroll
        for (int j = 0; j < 4; j++) {
            int e = c * 128 + j * 32 + eg;
            float nev = __ldg(&g_ne[e]);
            float rse = __ldg(&g_rsne[e]);
            #pragma unroll
            for (int i = 0; i < 4; i++) {
                int r = rg * 4 + i;
                float dot = acc[i][j];
                float dist = -2.0f * dot + nzs[r] + nev;
                float sim = dot * rsnzs[r] * rse;
                dout[OFF_SIM + (size_t)(row0 + r) * NEMB + e] = sim;
                if (dist < bv[i]) { bv[i] = dist; bi[i] = e; }
            }
        }
    }

    #pragma unroll
    for (int i = 0; i < 4; i++) {
        float v = bv[i];
        int idx = bi[i];
        #pragma unroll
        for (int off = 16; off > 0; off >>= 1) {
            float ov = __shfl_down_sync(0xffffffffu, v, off);
            int oi = __shfl_down_sync(0xffffffffu, idx, off);
            if (ov < v || (ov == v && oi < idx)) { v = ov; idx = oi; }
        }
        if (eg == 0) {
            int r = rg * 4 + i;
            int gr = row0 + r;
            dout[OFF_IDS + gr] = (float)idx;
            float s = 0.f;
            const float* cp = cb + (size_t)idx * 64;
            float* qp = zq + (size_t)gr * 64;
            #pragma unroll 8
            for (int ci = 0; ci < 64; ci++) {
                float cvv = __ldg(cp + ci);
                qp[ci] = cvv;
                float d = zs[r * 65 + ci] - cvv;
                s += d * d;
            }
            atomicAdd(&g_loss, sqrtf(s));
        }
    }
}

// ---------------- host orchestration ----------------
#define SMEM_RESK(DIL) ((ALIGN4((128 + 2 * (DIL)) * 65)) * 4)
#define SMEM_S2   ((ALIGN4(258 * 65) + 4096) * 4)
#define SMEM_TR   ((ALIGN4(130 * 65) + 16384) * 4)
#define SMEM_PROJ ((ALIGN4(258 * 65) + 192) * 4)

static inline void launch_res_pair(bool enc, int T,
    const float* w1, const float* b1, const float* w2, const float* b2,
    float* h, float* t)
{
    const int grid = NBATCH * (T >> 7);
    if (enc) {
        conv_res_kernel<3, false><<<grid, 256, SMEM_RESK(3)>>>(h, w1, b1, nullptr, t, T);
        conv_res_kernel<1, true ><<<grid, 256, SMEM_RESK(1)>>>(t, w2, b2, h, h, T);
    } else {
        conv_res_kernel<1, false><<<grid, 256, SMEM_RESK(1)>>>(h, w1, b1, nullptr, t, T);
        conv_res_kernel<3, true ><<<grid, 256, SMEM_RESK(3)>>>(t, w2, b2, h, h, T);
    }
}

extern "C" void kernel_launch(void* const* d_in, const int* in_sizes, int n_in,
                              void* d_out, int out_size)
{
    const float* x        = (const float*)d_in[0];
    const float* w_down0  = (const float*)d_in[1];
    const float* b_down0  = (const float*)d_in[2];
    const float* w_down   = (const float*)d_in[3];
    const float* b_down   = (const float*)d_in[4];
    const float* w_res_e  = (const float*)d_in[5];
    const float* b_res_e  = (const float*)d_in[6];
    const float* codebook = (const float*)d_in[7];
    const float* w_res_d  = (const float*)d_in[8];
    const float* b_res_d  = (const float*)d_in[9];
    const float* w_up     = (const float*)d_in[10];
    const float* b_up     = (const float*)d_in[11];
    const float* w_proj   = (const float*)d_in[12];
    const float* b_proj   = (const float*)d_in[13];
    float* out = (float*)d_out;

    float *A, *Bb;
    cudaGetSymbolAddress((void**)&A, g_A);
    cudaGetSymbolAddress((void**)&Bb, g_B);

    cudaFuncSetAttribute(conv_res_kernel<3, false>, cudaFuncAttributeMaxDynamicSharedMemorySize, SMEM_RESK(3));
    cudaFuncSetAttribute(conv_res_kernel<3, true >, cudaFuncAttributeMaxDynamicSharedMemorySize, SMEM_RESK(3));
    cudaFuncSetAttribute(conv_res_kernel<1, false>, cudaFuncAttributeMaxDynamicSharedMemorySize, SMEM_RESK(1));
    cudaFuncSetAttribute(conv_res_kernel<1, true >, cudaFuncAttributeMaxDynamicSharedMemorySize, SMEM_RESK(1));
    cudaFuncSetAttribute(conv_s2_kernel, cudaFuncAttributeMaxDynamicSharedMemorySize, SMEM_S2);
    cudaFuncSetAttribute(conv_tr_kernel, cudaFuncAttributeMaxDynamicSharedMemorySize, SMEM_TR);
    cudaFuncSetAttribute(proj_kernel,    cudaFuncAttributeMaxDynamicSharedMemorySize, SMEM_PROJ);

    zero_loss_kernel<<<1, 1>>>();
    ne_kernel<<<2, 256>>>(codebook);

    float* h = A;
    float* t = Bb;

    // ---------- encoder ----------
    down0_kernel<<<2048, 256>>>(x, w_down0, b_down0, h);
    int T = 32768;
    for (int blk = 0; blk < 3; blk++) {
        if (blk > 0) {
            int Tout = T >> 1;
            conv_s2_kernel<<<NBATCH * (Tout >> 7), 256, SMEM_S2>>>(
                h, w_down + (size_t)(blk - 1) * 16384, b_down + (blk - 1) * 64, t, Tout);
            T = Tout;
            float* tmp = h; h = t; t = tmp;
        }
        for (int r = 0; r < 4; r++) {
            const float* w1 = w_res_e + (size_t)((blk * 4 + r) * 2 + 0) * 12288;
            const float* w2 = w_res_e + (size_t)((blk * 4 + r) * 2 + 1) * 12288;
            const float* bb1 = b_res_e + ((blk * 4 + r) * 2 + 0) * 64;
            const float* bb2 = b_res_e + ((blk * 4 + r) * 2 + 1) * 64;
            launch_res_pair(true, T, w1, bb1, w2, bb2, h, t);
        }
    }

    // ---------- VQ (T = 8192) ----------
    vq_kernel<<<1024, 256>>>(h, codebook, t, out);
    loss_fin_kernel<<<1, 1>>>(out);
    { float* tmp = h; h = t; t = tmp; }   // h = z_q

    // ---------- decoder ----------
    for (int blk = 0; blk < 3; blk++) {
        for (int r = 0; r < 4; r++) {
            const float* w1 = w_res_d + (size_t)((blk * 4 + r) * 2 + 0) * 12288;
            const float* w2 = w_res_d + (size_t)((blk * 4 + r) * 2 + 1) * 12288;
            const float* bb1 = b_res_d + ((blk * 4 + r) * 2 + 0) * 64;
            const float* bb2 = b_res_d + ((blk * 4 + r) * 2 + 1) * 64;
            launch_res_pair(false, T, w1, bb1, w2, bb2, h, t);
        }
        int Tout = T << 1;
        conv_tr_kernel<<<NBATCH * (Tout >> 8), 256, SMEM_TR>>>(
            h, w_up + (size_t)blk * 16384, b_up + blk * 64, t, Tout);
        T = Tout;
        float* tmp = h; h = t; t = tmp;
    }

    // ---------- projection (T = 65536) ----------
    proj_kernel<<<NBATCH * (T >> 8), 256, SMEM_PROJ>>>(h, w_proj, b_proj, out, T);
}

// round 6
// speedup vs baseline: 1.4582x; 1.0327x over previous
#include <cuda_runtime.h>
#include <math.h>

// ---------------- constants ----------------
#define NBATCH 4
#define TTOP   65536
#define OFF_XHAT 0
#define OFF_LOSS 262144
#define OFF_IDS  262145
#define OFF_SIM  294913
#define NEMB 512

#define ALIGN4(n) (((n) + 3) & ~3)

// ---------------- scratch ----------------
__device__ float g_A[16777216];
__device__ float g_B[16777216];
__device__ float g_ne[NEMB];
__device__ float g_rsne[NEMB];
__device__ float g_loss;

__global__ void zero_loss_kernel() { g_loss = 0.f; }

__global__ void ne_kernel(const float* __restrict__ cb) {
    int e = blockIdx.x * blockDim.x + threadIdx.x;
    if (e < NEMB) {
        float s = 0.f;
        #pragma unroll 8
        for (int ci = 0; ci < 64; ci++) { float v = cb[e * 64 + ci]; s += v * v; }
        g_ne[e] = s;
        g_rsne[e] = rsqrtf(s);
    }
}

__global__ void loss_fin_kernel(float* __restrict__ out) {
    out[OFF_LOSS] = 1.25f * g_loss / 32768.0f;
}

// ---------------- first conv: Cin=1 -> 64, K=4, stride 2, ReLU ----------------
__global__ void __launch_bounds__(256) down0_kernel(
    const float* __restrict__ x, const float* __restrict__ w,
    const float* __restrict__ bias, float* __restrict__ y)
{
    __shared__ float ws[256];
    __shared__ float bs[64];
    int tid = threadIdx.x;
    ws[tid] = w[tid];
    if (tid < 64) bs[tid] = bias[tid];
    __syncthreads();

    int g = blockIdx.x * 256 + tid;
    int q = g & 3;
    int rest = g >> 2;
    int ot = rest & 32767;
    int b = rest >> 15;

    float acc[16];
    #pragma unroll
    for (int c = 0; c < 16; c++) acc[c] = bs[q * 16 + c];
    #pragma unroll
    for (int k = 0; k < 4; k++) {
        int t = 2 * ot - 1 + k;
        float xv = (t >= 0 && t < TTOP) ? x[(size_t)b * TTOP + t] : 0.f;
        #pragma unroll
        for (int c = 0; c < 16; c++) acc[c] += xv * ws[k * 64 + q * 16 + c];
    }
    float* op = y + ((size_t)(b * 32768 + ot)) * 64 + q * 16;
    #pragma unroll
    for (int c4 = 0; c4 < 4; c4++) {
        float4 o;
        o.x = fmaxf(acc[c4 * 4 + 0], 0.f);
        o.y = fmaxf(acc[c4 * 4 + 1], 0.f);
        o.z = fmaxf(acc[c4 * 4 + 2], 0.f);
        o.w = fmaxf(acc[c4 * 4 + 3], 0.f);
        *(float4*)(op + c4 * 4) = o;
    }
}

// ---------------- residual conv: K=3, dil DIL, 64->64, ReLU, optional +res ----
// 128-t tile, 256 threads, 8t x 4co per thread. x TRANSPOSED in smem
// ([64 ch][164 t], stride 164 = 4 mod 32 -> conflict-free STS.128 staging and
// LDS.128 window reads). Weights streamed via __ldg. 3 CTAs/SM.
#define XS_S 164

template<int DIL, bool RES>
__global__ void __launch_bounds__(256, 3) conv_res_kernel(
    const float* __restrict__ x, const float* __restrict__ w,
    const float* __restrict__ bias, const float* __restrict__ res,
    float* __restrict__ y, int T)
{
    constexpr int ROWS = 128 + 2 * DIL;
    constexpr int NQ = (ROWS + 3) >> 2;
    constexpr int W = 8 + 2 * DIL;          // window length actually used
    constexpr int NV = (W + 3) >> 2;        // float4 loads covering window

    extern __shared__ float smem[];
    float* xsT = smem;   // [64][XS_S]

    const int tid = threadIdx.x;
    const int tilesPerB = T >> 7;
    const int b = blockIdx.x / tilesPerB;
    const int t0 = (blockIdx.x - b * tilesPerB) << 7;
    const float* xb = x + (size_t)b * T * 64;

    // stage x transposed: thread gathers 4 time-consecutive scalars for one ci
    // (each of the 4 global loads is a coalesced 128B line across 32 ci lanes),
    // writes one conflict-free STS.128.
    for (int idx = tid; idx < 64 * NQ; idx += 256) {
        int ci = idx & 63;
        int rb = (idx >> 6) << 2;
        int gt = t0 - DIL + rb;
        float4 v;
        v.x = (gt + 0 >= 0 && gt + 0 < T) ? xb[(size_t)(gt + 0) * 64 + ci] : 0.f;
        v.y = (gt + 1 >= 0 && gt + 1 < T) ? xb[(size_t)(gt + 1) * 64 + ci] : 0.f;
        v.z = (gt + 2 >= 0 && gt + 2 < T) ? xb[(size_t)(gt + 2) * 64 + ci] : 0.f;
        v.w = (gt + 3 >= 0 && gt + 3 < T) ? xb[(size_t)(gt + 3) * 64 + ci] : 0.f;
        *(float4*)&xsT[ci * XS_S + rb] = v;
    }
    __syncthreads();

    const int tg = tid >> 4;        // 16 time groups of 8
    const int cg = tid & 15;        // 16 co groups of 4
    const int tb = tg << 3;
    const int co0 = cg << 2;

    float acc[8][4];
    #pragma unroll
    for (int i = 0; i < 8; i++)
        #pragma unroll
        for (int j = 0; j < 4; j++) acc[i][j] = 0.f;

    #pragma unroll 2
    for (int ci = 0; ci < 64; ci++) {
        const float4* xr = (const float4*)&xsT[ci * XS_S + tb];
        float xw[NV * 4];
        #pragma unroll
        for (int v = 0; v < NV; v++) {
            float4 c = xr[v];
            xw[v * 4 + 0] = c.x; xw[v * 4 + 1] = c.y;
            xw[v * 4 + 2] = c.z; xw[v * 4 + 3] = c.w;
        }

        #pragma unroll
        for (int k = 0; k < 3; k++) {
            float4 wa = __ldg((const float4*)(w + k * 4096 + ci * 64 + co0));
            #pragma unroll
            for (int i = 0; i < 8; i++) {
                float xv = xw[i + k * DIL];
                acc[i][0] += xv * wa.x; acc[i][1] += xv * wa.y;
                acc[i][2] += xv * wa.z; acc[i][3] += xv * wa.w;
            }
        }
    }

    float4 bv = *(const float4*)(bias + co0);
    #pragma unroll
    for (int i = 0; i < 8; i++) {
        int gt = t0 + tb + i;
        float* op = y + ((size_t)b * T + gt) * 64 + co0;
        float4 o;
        o.x = fmaxf(acc[i][0] + bv.x, 0.f);
        o.y = fmaxf(acc[i][1] + bv.y, 0.f);
        o.z = fmaxf(acc[i][2] + bv.z, 0.f);
        o.w = fmaxf(acc[i][3] + bv.w, 0.f);
        if (RES) {
            float4 r0 = *(const float4*)(res + ((size_t)b * T + gt) * 64 + co0);
            o.x += r0.x; o.y += r0.y; o.z += r0.z; o.w += r0.w;
        }
        *(float4*)op = o;
    }
}

// ---------------- strided down conv: K=4, stride 2, 64->64, ReLU ----------------
__global__ void __launch_bounds__(256, 2) conv_s2_kernel(
    const float* __restrict__ x, const float* __restrict__ w,
    const float* __restrict__ bias, float* __restrict__ y, int Tout)
{
    extern __shared__ float smem[];
    float* xs = smem;                           // [258][65]
    float* wsm = smem + ALIGN4(258 * 65);       // [64][64]
    const int Tin = Tout << 1;
    const int tid = threadIdx.x;
    const int tilesPerB = Tout >> 7;
    const int b = blockIdx.x / tilesPerB;
    const int t0 = (blockIdx.x - b * tilesPerB) << 7;
    const float* xb = x + (size_t)b * Tin * 64;

    for (int idx = tid; idx < 258 * 16; idx += 256) {
        int r = idx >> 4, c4 = idx & 15;
        int gt = 2 * t0 - 1 + r;
        float4 v = make_float4(0.f, 0.f, 0.f, 0.f);
        if (gt >= 0 && gt < Tin) v = *(const float4*)(xb + (size_t)gt * 64 + c4 * 4);
        float* d = &xs[r * 65 + c4 * 4];
        d[0] = v.x; d[1] = v.y; d[2] = v.z; d[3] = v.w;
    }

    const int tg = tid >> 3;
    const int cg = tid & 7;
    float acc[4][8];
    #pragma unroll
    for (int i = 0; i < 4; i++)
        #pragma unroll
        for (int j = 0; j < 8; j++) acc[i][j] = 0.f;

    for (int k = 0; k < 4; k++) {
        __syncthreads();
        {
            const float4* wg = (const float4*)(w + k * 4096);
            float4* wd = (float4*)wsm;
            for (int idx = tid; idx < 1024; idx += 256) wd[idx] = wg[idx];
        }
        __syncthreads();
        const float4* ws4 = (const float4*)wsm;
        #pragma unroll 2
        for (int ci = 0; ci < 64; ci++) {
            float4 wa = ws4[ci * 16 + cg * 2];
            float4 wb = ws4[ci * 16 + cg * 2 + 1];
            #pragma unroll
            for (int i = 0; i < 4; i++) {
                float xv = xs[(2 * (tg * 4 + i) + k) * 65 + ci];
                acc[i][0] += xv * wa.x; acc[i][1] += xv * wa.y;
                acc[i][2] += xv * wa.z; acc[i][3] += xv * wa.w;
                acc[i][4] += xv * wb.x; acc[i][5] += xv * wb.y;
                acc[i][6] += xv * wb.z; acc[i][7] += xv * wb.w;
            }
        }
    }

    const int co0 = cg * 8;
    float4 bv0 = *(const float4*)(bias + co0);
    float4 bv1 = *(const float4*)(bias + co0 + 4);
    #pragma unroll
    for (int i = 0; i < 4; i++) {
        int gt = t0 + tg * 4 + i;
        float* op = y + ((size_t)b * Tout + gt) * 64 + co0;
        float4 o0, o1;
        o0.x = fmaxf(acc[i][0] + bv0.x, 0.f);
        o0.y = fmaxf(acc[i][1] + bv0.y, 0.f);
        o0.z = fmaxf(acc[i][2] + bv0.z, 0.f);
        o0.w = fmaxf(acc[i][3] + bv0.w, 0.f);
        o1.x = fmaxf(acc[i][4] + bv1.x, 0.f);
        o1.y = fmaxf(acc[i][5] + bv1.y, 0.f);
        o1.z = fmaxf(acc[i][6] + bv1.z, 0.f);
        o1.w = fmaxf(acc[i][7] + bv1.w, 0.f);
        *(float4*)op = o0;
        *(float4*)(op + 4) = o1;
    }
}

// ---------------- transposed conv: K=4, stride 2, 64->64, ReLU ----------------
__global__ void __launch_bounds__(256, 2) conv_tr_kernel(
    const float* __restrict__ x, const float* __restrict__ w,
    const float* __restrict__ bias, float* __restrict__ y, int Tout)
{
    extern __shared__ float smem[];
    float* xs = smem;                           // [130][65]
    float* wsm = smem + ALIGN4(130 * 65);       // [4][64][64]
    const int Tin = Tout >> 1;
    const int tid = threadIdx.x;
    const int tilesPerB = Tout >> 8;
    const int b = blockIdx.x / tilesPerB;
    const int t0 = (blockIdx.x - b * tilesPerB) << 8;
    const float* xb = x + (size_t)b * Tin * 64;
    const int in0 = (t0 >> 1) - 1;

    for (int idx = tid; idx < 130 * 16; idx += 256) {
        int r = idx >> 4, c4 = idx & 15;
        int gt = in0 + r;
        float4 v = make_float4(0.f, 0.f, 0.f, 0.f);
        if (gt >= 0 && gt < Tin) v = *(const float4*)(xb + (size_t)gt * 64 + c4 * 4);
        float* d = &xs[r * 65 + c4 * 4];
        d[0] = v.x; d[1] = v.y; d[2] = v.z; d[3] = v.w;
    }
    {
        const float4* wg = (const float4*)w;
        float4* wd = (float4*)wsm;
        for (int idx = tid; idx < 4096; idx += 256) wd[idx] = wg[idx];
    }
    __syncthreads();

    const int tg = tid >> 3;
    const int cg = tid & 7;
    float acc[8][8];
    #pragma unroll
    for (int i = 0; i < 8; i++)
        #pragma unroll
        for (int j = 0; j < 8; j++) acc[i][j] = 0.f;

    const float4* ws4 = (const float4*)wsm;
    #pragma unroll 2
    for (int ci = 0; ci < 64; ci++) {
        float xv[6];
        #pragma unroll
        for (int m = 0; m < 6; m++) xv[m] = xs[(tg * 4 + m) * 65 + ci];
        {
            float4 wa0 = ws4[ci * 16 + cg * 2];
            float4 wb0 = ws4[ci * 16 + cg * 2 + 1];
            float4 wa2 = ws4[2 * 1024 + ci * 16 + cg * 2];
            float4 wb2 = ws4[2 * 1024 + ci * 16 + cg * 2 + 1];
            #pragma unroll
            for (int ii = 0; ii < 4; ii++) {
                const int i = 2 * ii;
                float xa = xv[ii], xbv = xv[ii + 1];
                acc[i][0] += xa * wa0.x + xbv * wa2.x;
                acc[i][1] += xa * wa0.y + xbv * wa2.y;
                acc[i][2] += xa * wa0.z + xbv * wa2.z;
                acc[i][3] += xa * wa0.w + xbv * wa2.w;
                acc[i][4] += xa * wb0.x + xbv * wb2.x;
                acc[i][5] += xa * wb0.y + xbv * wb2.y;
                acc[i][6] += xa * wb0.z + xbv * wb2.z;
                acc[i][7] += xa * wb0.w + xbv * wb2.w;
            }
        }
        {
            float4 wa1 = ws4[1024 + ci * 16 + cg * 2];
            float4 wb1 = ws4[1024 + ci * 16 + cg * 2 + 1];
            float4 wa3 = ws4[3 * 1024 + ci * 16 + cg * 2];
            float4 wb3 = ws4[3 * 1024 + ci * 16 + cg * 2 + 1];
            #pragma unroll
            for (int ii = 0; ii < 4; ii++) {
                const int i = 2 * ii + 1;
                float xa = xv[ii + 1], xbv = xv[ii + 2];
                acc[i][0] += xa * wa1.x + xbv * wa3.x;
                acc[i][1] += xa * wa1.y + xbv * wa3.y;
                acc[i][2] += xa * wa1.z + xbv * wa3.z;
                acc[i][3] += xa * wa1.w + xbv * wa3.w;
                acc[i][4] += xa * wb1.x + xbv * wb3.x;
                acc[i][5] += xa * wb1.y + xbv * wb3.y;
                acc[i][6] += xa * wb1.z + xbv * wb3.z;
                acc[i][7] += xa * wb1.w + xbv * wb3.w;
            }
        }
    }

    const int co0 = cg * 8;
    float4 bv0 = *(const float4*)(bias + co0);
    float4 bv1 = *(const float4*)(bias + co0 + 4);
    #pragma unroll
    for (int i = 0; i < 8; i++) {
        int gt = t0 + tg * 8 + i;
        float* op = y + ((size_t)b * Tout + gt) * 64 + co0;
        float4 o0, o1;
        o0.x = fmaxf(acc[i][0] + bv0.x, 0.f);
        o0.y = fmaxf(acc[i][1] + bv0.y, 0.f);
        o0.z = fmaxf(acc[i][2] + bv0.z, 0.f);
        o0.w = fmaxf(acc[i][3] + bv0.w, 0.f);
        o1.x = fmaxf(acc[i][4] + bv1.x, 0.f);
        o1.y = fmaxf(acc[i][5] + bv1.y, 0.f);
        o1.z = fmaxf(acc[i][6] + bv1.z, 0.f);
        o1.w = fmaxf(acc[i][7] + bv1.w, 0.f);
        *(float4*)op = o0;
        *(float4*)(op + 4) = o1;
    }
}

// ---------------- final projection: K=3, dil 1, 64->1, linear ----------------
__global__ void __launch_bounds__(256) proj_kernel(
    const float* __restrict__ x, const float* __restrict__ w,
    const float* __restrict__ bias, float* __restrict__ out, int T)
{
    extern __shared__ float smem[];
    float* xs = smem;                           // [258][65]
    float* ws = smem + ALIGN4(258 * 65);        // [192]
    const int tid = threadIdx.x;
    const int tilesPerB = T >> 8;
    const int b = blockIdx.x / tilesPerB;
    const int t0 = (blockIdx.x - b * tilesPerB) << 8;
    const float* xb = x + (size_t)b * T * 64;

    for (int idx = tid; idx < 258 * 16; idx += 256) {
        int r = idx >> 4, c4 = idx & 15;
        int gt = t0 - 1 + r;
        float4 v = make_float4(0.f, 0.f, 0.f, 0.f);
        if (gt >= 0 && gt < T) v = *(const float4*)(xb + (size_t)gt * 64 + c4 * 4);
        float* d = &xs[r * 65 + c4 * 4];
        d[0] = v.x; d[1] = v.y; d[2] = v.z; d[3] = v.w;
    }
    if (tid < 192) ws[tid] = w[tid];
    __syncthreads();

    float acc = 0.f;
    #pragma unroll
    for (int k = 0; k < 3; k++) {
        #pragma unroll 8
        for (int ci = 0; ci < 64; ci++)
            acc += xs[(tid + k) * 65 + ci] * ws[k * 64 + ci];
    }
    out[OFF_XHAT + (size_t)b * T + t0 + tid] = acc + bias[0];
}

// ---------------- VQ ----------------
__global__ void __launch_bounds__(256) vq_kernel(
    const float* __restrict__ ze, const float* __restrict__ cb,
    float* __restrict__ zq, float* __restrict__ dout)
{
    __shared__ float zs[32 * 65];
    __shared__ float cbs[128 * 65];
    __shared__ float nzs[32], rsnzs[32];

    const int tid = threadIdx.x;
    const int rg = tid >> 5;
    const int eg = tid & 31;
    const int row0 = blockIdx.x * 32;

    for (int idx = tid; idx < 32 * 16; idx += 256) {
        int r = idx >> 4, c4 = idx & 15;
        float4 v = *(const float4*)(ze + (size_t)(row0 + r) * 64 + c4 * 4);
        float* d = &zs[r * 65 + c4 * 4];
        d[0] = v.x; d[1] = v.y; d[2] = v.z; d[3] = v.w;
    }
    __syncthreads();
    if (tid < 32) {
        float s = 0.f;
        #pragma unroll 8
        for (int ci = 0; ci < 64; ci++) { float v = zs[tid * 65 + ci]; s += v * v; }
        nzs[tid] = s;
        rsnzs[tid] = rsqrtf(s);
    }

    float bv[4] = {3.4e38f, 3.4e38f, 3.4e38f, 3.4e38f};
    int bi[4] = {0, 0, 0, 0};

    for (int c = 0; c < 4; c++) {
        __syncthreads();
        for (int idx = tid; idx < 128 * 16; idx += 256) {
            int e = idx >> 4, c4 = idx & 15;
            float4 v = *(const float4*)(cb + (size_t)(c * 128 + e) * 64 + c4 * 4);
            float* d = &cbs[e * 65 + c4 * 4];
            d[0] = v.x; d[1] = v.y; d[2] = v.z; d[3] = v.w;
        }
        __syncthreads();

        float acc[4][4];
        #pragma unroll
        for (int i = 0; i < 4; i++)
            #pragma unroll
            for (int j = 0; j < 4; j++) acc[i][j] = 0.f;

        #pragma unroll 4
        for (int ci = 0; ci < 64; ci++) {
            float zv[4], cv[4];
            #pragma unroll
            for (int i = 0; i < 4; i++) zv[i] = zs[(rg * 4 + i) * 65 + ci];
            #pragma unroll
            for (int j = 0; j < 4; j++) cv[j] = cbs[(j * 32 + eg) * 65 + ci];
            #pragma unroll
            for (int i = 0; i < 4; i++)
                #pragma unroll
                for (int j = 0; j < 4; j++) acc[i][j] += zv[i] * cv[j];
        }

        #pragma unroll
        for (int j = 0; j < 4; j++) {
            int e = c * 128 + j * 32 + eg;
            float nev = __ldg(&g_ne[e]);
            float rse = __ldg(&g_rsne[e]);
            #pragma unroll
            for (int i = 0; i < 4; i++) {
                int r = rg * 4 + i;
                float dot = acc[i][j];
                float dist = -2.0f * dot + nzs[r] + nev;
                float sim = dot * rsnzs[r] * rse;
                dout[OFF_SIM + (size_t)(row0 + r) * NEMB + e] = sim;
                if (dist < bv[i]) { bv[i] = dist; bi[i] = e; }
            }
        }
    }

    #pragma unroll
    for (int i = 0; i < 4; i++) {
        float v = bv[i];
        int idx = bi[i];
        #pragma unroll
        for (int off = 16; off > 0; off >>= 1) {
            float ov = __shfl_down_sync(0xffffffffu, v, off);
            int oi = __shfl_down_sync(0xffffffffu, idx, off);
            if (ov < v || (ov == v && oi < idx)) { v = ov; idx = oi; }
        }
        if (eg == 0) {
            int r = rg * 4 + i;
            int gr = row0 + r;
            dout[OFF_IDS + gr] = (float)idx;
            float s = 0.f;
            const float* cp = cb + (size_t)idx * 64;
            float* qp = zq + (size_t)gr * 64;
            #pragma unroll 8
            for (int ci = 0; ci < 64; ci++) {
                float cvv = __ldg(cp + ci);
                qp[ci] = cvv;
                float d = zs[r * 65 + ci] - cvv;
                s += d * d;
            }
            atomicAdd(&g_loss, sqrtf(s));
        }
    }
}

// ---------------- host orchestration ----------------
#define SMEM_RESK (64 * XS_S * 4)
#define SMEM_S2   ((ALIGN4(258 * 65) + 4096) * 4)
#define SMEM_TR   ((ALIGN4(130 * 65) + 16384) * 4)
#define SMEM_PROJ ((ALIGN4(258 * 65) + 192) * 4)

static inline void launch_res_pair(bool enc, int T,
    const float* w1, const float* b1, const float* w2, const float* b2,
    float* h, float* t)
{
    const int grid = NBATCH * (T >> 7);
    if (enc) {
        conv_res_kernel<3, false><<<grid, 256, SMEM_RESK>>>(h, w1, b1, nullptr, t, T);
        conv_res_kernel<1, true ><<<grid, 256, SMEM_RESK>>>(t, w2, b2, h, h, T);
    } else {
        conv_res_kernel<1, false><<<grid, 256, SMEM_RESK>>>(h, w1, b1, nullptr, t, T);
        conv_res_kernel<3, true ><<<grid, 256, SMEM_RESK>>>(t, w2, b2, h, h, T);
    }
}

extern "C" void kernel_launch(void* const* d_in, const int* in_sizes, int n_in,
                              void* d_out, int out_size)
{
    const float* x        = (const float*)d_in[0];
    const float* w_down0  = (const float*)d_in[1];
    const float* b_down0  = (const float*)d_in[2];
    const float* w_down   = (const float*)d_in[3];
    const float* b_down   = (const float*)d_in[4];
    const float* w_res_e  = (const float*)d_in[5];
    const float* b_res_e  = (const float*)d_in[6];
    const float* codebook = (const float*)d_in[7];
    const float* w_res_d  = (const float*)d_in[8];
    const float* b_res_d  = (const float*)d_in[9];
    const float* w_up     = (const float*)d_in[10];
    const float* b_up     = (const float*)d_in[11];
    const float* w_proj   = (const float*)d_in[12];
    const float* b_proj   = (const float*)d_in[13];
    float* out = (float*)d_out;

    float *A, *Bb;
    cudaGetSymbolAddress((void**)&A, g_A);
    cudaGetSymbolAddress((void**)&Bb, g_B);

    cudaFuncSetAttribute(conv_res_kernel<3, false>, cudaFuncAttributeMaxDynamicSharedMemorySize, SMEM_RESK);
    cudaFuncSetAttribute(conv_res_kernel<3, true >, cudaFuncAttributeMaxDynamicSharedMemorySize, SMEM_RESK);
    cudaFuncSetAttribute(conv_res_kernel<1, false>, cudaFuncAttributeMaxDynamicSharedMemorySize, SMEM_RESK);
    cudaFuncSetAttribute(conv_res_kernel<1, true >, cudaFuncAttributeMaxDynamicSharedMemorySize, SMEM_RESK);
    cudaFuncSetAttribute(conv_s2_kernel, cudaFuncAttributeMaxDynamicSharedMemorySize, SMEM_S2);
    cudaFuncSetAttribute(conv_tr_kernel, cudaFuncAttributeMaxDynamicSharedMemorySize, SMEM_TR);
    cudaFuncSetAttribute(proj_kernel,    cudaFuncAttributeMaxDynamicSharedMemorySize, SMEM_PROJ);

    zero_loss_kernel<<<1, 1>>>();
    ne_kernel<<<2, 256>>>(codebook);

    float* h = A;
    float* t = Bb;

    // ---------- encoder ----------
    down0_kernel<<<2048, 256>>>(x, w_down0, b_down0, h);
    int T = 32768;
    for (int blk = 0; blk < 3; blk++) {
        if (blk > 0) {
            int Tout = T >> 1;
            conv_s2_kernel<<<NBATCH * (Tout >> 7), 256, SMEM_S2>>>(
                h, w_down + (size_t)(blk - 1) * 16384, b_down + (blk - 1) * 64, t, Tout);
            T = Tout;
            float* tmp = h; h = t; t = tmp;
        }
        for (int r = 0; r < 4; r++) {
            const float* w1 = w_res_e + (size_t)((blk * 4 + r) * 2 + 0) * 12288;
            const float* w2 = w_res_e + (size_t)((blk * 4 + r) * 2 + 1) * 12288;
            const float* bb1 = b_res_e + ((blk * 4 + r) * 2 + 0) * 64;
            const float* bb2 = b_res_e + ((blk * 4 + r) * 2 + 1) * 64;
            launch_res_pair(true, T, w1, bb1, w2, bb2, h, t);
        }
    }

    // ---------- VQ (T = 8192) ----------
    vq_kernel<<<1024, 256>>>(h, codebook, t, out);
    loss_fin_kernel<<<1, 1>>>(out);
    { float* tmp = h; h = t; t = tmp; }   // h = z_q

    // ---------- decoder ----------
    for (int blk = 0; blk < 3; blk++) {
        for (int r = 0; r < 4; r++) {
            const float* w1 = w_res_d + (size_t)((blk * 4 + r) * 2 + 0) * 12288;
            const float* w2 = w_res_d + (size_t)((blk * 4 + r) * 2 + 1) * 12288;
            const float* bb1 = b_res_d + ((blk * 4 + r) * 2 + 0) * 64;
            const float* bb2 = b_res_d + ((blk * 4 + r) * 2 + 1) * 64;
            launch_res_pair(false, T, w1, bb1, w2, bb2, h, t);
        }
        int Tout = T << 1;
        conv_tr_kernel<<<NBATCH * (Tout >> 8), 256, SMEM_TR>>>(
            h, w_up + (size_t)blk * 16384, b_up + blk * 64, t, Tout);
        T = Tout;
        float* tmp = h; h = t; t = tmp;
    }

    // ---------- projection (T = 65536) ----------
    proj_kernel<<<NBATCH * (T >> 8), 256, SMEM_PROJ>>>(h, w_proj, b_proj, out, T);
}